// round 8
// baseline (speedup 1.0000x reference)
#include <cuda_runtime.h>
#include <cuda_bf16.h>
#include <math.h>
#include <stdint.h>

// Problem constants
#define B_   16
#define L_   128
#define KW   8
#define NPAIR 2104
#define GCN  512
#define PE   64
#define PF   1088
#define PFP  1152
#define M_   2048
#define NREL 17
#define NT   48           // k-tiles: 3 segments x 16 tiles of 32

// ---------------- scratch ----------------------------------------------------
__device__ float g_Aemo[M_ * PF];
__device__ float g_Acau[M_ * PF];
__device__ float g_Apos[NREL * PF];
__device__ float g_f[NREL * PE];
__device__ int   g_poff[L_];
__device__ __nv_bfloat16 g_Ahi[2][M_ * GCN];
__device__ __nv_bfloat16 g_Alo[2][M_ * GCN];
__device__ __nv_bfloat16 g_Bhi[2][PFP * GCN];
__device__ __nv_bfloat16 g_Blo[2][PFP * GCN];

// ---------------- init: pair offsets + emo_cau_pos tail ----------------------
__global__ void init_pairs_kernel(float* __restrict__ out, int out_size) {
    int i = threadIdx.x;
    if (i >= L_) return;
    int off = 0;
    for (int t = 0; t < i; t++) {
        int lo = t - KW; if (lo < 0) lo = 0;
        int hi = t + KW; if (hi > L_ - 1) hi = L_ - 1;
        off += hi - lo + 1;
    }
    g_poff[i] = off;
    int lo = i - KW; if (lo < 0) lo = 0;
    int hi = i + KW; if (hi > L_ - 1) hi = L_ - 1;
    if (out_size == B_ * NPAIR + 2 * NPAIR) {
        for (int j = lo; j <= hi; j++) {
            int p = off + (j - lo);
            out[B_ * NPAIR + 2 * p + 0] = (float)(i + 1);
            out[B_ * NPAIR + 2 * p + 1] = (float)(j + 1);
        }
    }
}

// ---------------- init: smoothed positional table f [17 x 64] ----------------
__global__ void init_f_kernel(const float* __restrict__ pos_emb) {
    int idx = blockIdx.x * blockDim.x + threadIdx.x;
    if (idx >= NREL * PE) return;
    int r = idx / PE;
    int e = idx % PE;
    float s = 0.f;
    #pragma unroll
    for (int d = 0; d < NREL; d++) {
        int ad = d - KW; if (ad < 0) ad = -ad;
        float cnt = (float)(L_ - ad);
        int dd = r - d;
        float w = cnt * expf(-(float)(dd * dd));
        s += w * pos_emb[d * PE + e];
    }
    g_f[idx] = s;
}

// ---------------- init: A_pos (includes b1) ----------------------------------
__global__ void init_apos_kernel(const float* __restrict__ W1,
                                 const float* __restrict__ b1) {
    int idx = blockIdx.x * blockDim.x + threadIdx.x;
    if (idx >= NREL * PF) return;
    int r = idx / PF;
    int g = idx % PF;
    float s = b1[g];
    const float* w = W1 + g * PF + 2 * GCN;
    const float* f = g_f + r * PE;
    #pragma unroll 8
    for (int e = 0; e < PE; e++) s += f[e] * w[e];
    g_Apos[idx] = s;
}

// ---------------- convert: X -> hi/lo bf16 (8 elems/thread, 16B stores) ------
__global__ void conv_x_kernel(const float* __restrict__ Xe,
                              const float* __restrict__ Xc) {
    int idx = blockIdx.x * blockDim.x + threadIdx.x;     // 8-elem chunk index
    if (idx >= M_ * GCN / 8) return;
    #pragma unroll
    for (int z = 0; z < 2; z++) {
        const float* X = z ? Xc : Xe;
        float4 v0 = *(const float4*)(X + (size_t)idx * 8);
        float4 v1 = *(const float4*)(X + (size_t)idx * 8 + 4);
        __nv_bfloat16 h[8], l[8];
        float f[8] = {v0.x, v0.y, v0.z, v0.w, v1.x, v1.y, v1.z, v1.w};
        #pragma unroll
        for (int e = 0; e < 8; e++) {
            h[e] = __float2bfloat16(f[e]);
            l[e] = __float2bfloat16(f[e] - __bfloat162float(h[e]));
        }
        *(uint4*)(&g_Ahi[z][(size_t)idx * 8]) = *(const uint4*)h;
        *(uint4*)(&g_Alo[z][(size_t)idx * 8]) = *(const uint4*)l;
    }
}

// ---------------- convert: W1 -> hi/lo bf16 (8 elems/thread, 16B stores) -----
__global__ void conv_w_kernel(const float* __restrict__ W1) {
    int idx = blockIdx.x * blockDim.x + threadIdx.x;     // 8-elem chunk over PF*GCN
    if (idx >= PF * GCN / 8) return;
    int g = idx / (GCN / 8), kq = idx % (GCN / 8);
    #pragma unroll
    for (int z = 0; z < 2; z++) {
        const float* src = W1 + (size_t)g * PF + z * GCN + kq * 8;
        float4 v0 = *(const float4*)(src);
        float4 v1 = *(const float4*)(src + 4);
        __nv_bfloat16 h[8], l[8];
        float f[8] = {v0.x, v0.y, v0.z, v0.w, v1.x, v1.y, v1.z, v1.w};
        #pragma unroll
        for (int e = 0; e < 8; e++) {
            h[e] = __float2bfloat16(f[e]);
            l[e] = __float2bfloat16(f[e] - __bfloat162float(h[e]));
        }
        *(uint4*)(&g_Bhi[z][(size_t)g * GCN + kq * 8]) = *(const uint4*)h;
        *(uint4*)(&g_Blo[z][(size_t)g * GCN + kq * 8]) = *(const uint4*)l;
    }
}

// ---------------- bf16 tensor-core GEMM (128x128x32, ldmatrix, 3-stage) ------
#define BM 128
#define BN 128
#define BK 32
#define SSTR 40
#define NSTAGE 3
#define SA_ELEMS (BM * SSTR)
#define SB_ELEMS (BN * SSTR)
#define STAGE_ELEMS (SA_ELEMS + SB_ELEMS)

__device__ __forceinline__ void cp16(void* smem, const void* g) {
    unsigned s = (unsigned)__cvta_generic_to_shared(smem);
    asm volatile("cp.async.cg.shared.global [%0], [%1], 16;\n" :: "r"(s), "l"(g));
}
#define CP_COMMIT() asm volatile("cp.async.commit_group;\n" ::: "memory")
#define CP_WAIT1()  asm volatile("cp.async.wait_group 1;\n" ::: "memory")

__device__ __forceinline__ void ldsm4(unsigned& r0, unsigned& r1,
                                      unsigned& r2, unsigned& r3,
                                      const __nv_bfloat16* p) {
    unsigned a = (unsigned)__cvta_generic_to_shared(p);
    asm volatile("ldmatrix.sync.aligned.m8n8.x4.shared.b16 {%0,%1,%2,%3}, [%4];\n"
                 : "=r"(r0), "=r"(r1), "=r"(r2), "=r"(r3) : "r"(a));
}

extern __shared__ __align__(16) unsigned char dynraw[];

__global__ void __launch_bounds__(256, 2)
mma_gemm_kernel() {
    __nv_bfloat16* dynsmem = (__nv_bfloat16*)dynraw;
    const int z = blockIdx.z;
    const __nv_bfloat16* __restrict__ Ahi = g_Ahi[z];
    const __nv_bfloat16* __restrict__ Alo = g_Alo[z];
    const __nv_bfloat16* __restrict__ Bhi = g_Bhi[z];
    const __nv_bfloat16* __restrict__ Blo = g_Blo[z];
    float* __restrict__ C = z ? g_Acau : g_Aemo;

    const int tid  = threadIdx.x;
    const int lane = tid & 31;
    const int wid  = tid >> 5;
    const int wmBase = (wid & 1) * 64;
    const int wnBase = (wid >> 1) * 32;
    const int m0 = blockIdx.y * BM;
    const int n0 = blockIdx.x * BN;

    const int aRow = (lane & 7) + ((lane >> 3) & 1) * 8;
    const int aK   = (lane >> 4) * 8;
    const int bRow = (lane & 7) + (lane >> 4) * 8;
    const int bK   = ((lane >> 3) & 1) * 8;

    float acc[4][4][4];
    #pragma unroll
    for (int mt = 0; mt < 4; mt++)
        #pragma unroll
        for (int nt = 0; nt < 4; nt++)
            #pragma unroll
            for (int e = 0; e < 4; e++) acc[mt][nt][e] = 0.f;

    auto load_stage = [&](int kt, int s) {
        const int seg = kt >> 4;
        const int kc  = (kt & 15) * BK;
        const __nv_bfloat16* __restrict__ Asrc = (seg < 2) ? Ahi : Alo;
        const __nv_bfloat16* __restrict__ Bsrc = (seg == 1) ? Blo : Bhi;
        __nv_bfloat16* sA = dynsmem + s * STAGE_ELEMS;
        __nv_bfloat16* sB = sA + SA_ELEMS;
        #pragma unroll
        for (int l = 0; l < 2; l++) {
            int q = tid + l * 256;
            int row = q >> 2, c8 = (q & 3) * 8;
            cp16(&sA[row * SSTR + c8],
                 Asrc + (size_t)(m0 + row) * GCN + kc + c8);
        }
        #pragma unroll
        for (int l = 0; l < 2; l++) {
            int q = tid + l * 256;
            int row = q >> 2, c8 = (q & 3) * 8;
            cp16(&sB[row * SSTR + c8],
                 Bsrc + (size_t)(n0 + row) * GCN + kc + c8);
        }
    };

    load_stage(0, 0); CP_COMMIT();
    load_stage(1, 1); CP_COMMIT();

    for (int kt = 0; kt < NT; kt++) {
        CP_WAIT1();
        __syncthreads();
        if (kt + 2 < NT) load_stage(kt + 2, (kt + 2) % NSTAGE);
        CP_COMMIT();

        const int s = kt % NSTAGE;
        const __nv_bfloat16* sA = dynsmem + s * STAGE_ELEMS;
        const __nv_bfloat16* sB = sA + SA_ELEMS;

        #pragma unroll
        for (int kk = 0; kk < BK; kk += 16) {
            unsigned a[4][4], b[2][4];
            #pragma unroll
            for (int mt = 0; mt < 4; mt++)
                ldsm4(a[mt][0], a[mt][1], a[mt][2], a[mt][3],
                      &sA[(wmBase + mt * 16 + aRow) * SSTR + kk + aK]);
            #pragma unroll
            for (int ntp = 0; ntp < 2; ntp++)
                ldsm4(b[ntp][0], b[ntp][1], b[ntp][2], b[ntp][3],
                      &sB[(wnBase + ntp * 16 + bRow) * SSTR + kk + bK]);
            #pragma unroll
            for (int mt = 0; mt < 4; mt++)
                #pragma unroll
                for (int nt = 0; nt < 4; nt++) {
                    unsigned b0 = b[nt >> 1][(nt & 1) * 2];
                    unsigned b1 = b[nt >> 1][(nt & 1) * 2 + 1];
                    asm volatile(
                        "mma.sync.aligned.m16n8k16.row.col.f32.bf16.bf16.f32 "
                        "{%0,%1,%2,%3}, {%4,%5,%6,%7}, {%8,%9}, {%0,%1,%2,%3};\n"
                        : "+f"(acc[mt][nt][0]), "+f"(acc[mt][nt][1]),
                          "+f"(acc[mt][nt][2]), "+f"(acc[mt][nt][3])
                        : "r"(a[mt][0]), "r"(a[mt][1]), "r"(a[mt][2]), "r"(a[mt][3]),
                          "r"(b0), "r"(b1));
                }
        }
    }

    #pragma unroll
    for (int mt = 0; mt < 4; mt++) {
        int row = m0 + wmBase + mt * 16 + (lane >> 2);
        #pragma unroll
        for (int nt = 0; nt < 4; nt++) {
            int col = n0 + wnBase + nt * 8 + (lane & 3) * 2;
            if (col < PF) {
                *(float2*)&C[(size_t)row * PF + col] =
                    make_float2(acc[mt][nt][0], acc[mt][nt][1]);
                *(float2*)&C[(size_t)(row + 8) * PF + col] =
                    make_float2(acc[mt][nt][2], acc[mt][nt][3]);
            }
        }
    }
}

// ---------------- epilogue: warp per (b, i); emo row + W2 in registers -------
__global__ void __launch_bounds__(256)
epilogue_kernel(const float* __restrict__ W2, const float* __restrict__ b2,
                float* __restrict__ out) {
    int gw = (blockIdx.x * blockDim.x + threadIdx.x) >> 5;   // 0..2047
    int lane = threadIdx.x & 31;
    if (gw >= B_ * L_) return;
    int b = gw >> 7;          // / L_
    int i = gw & (L_ - 1);

    // emo row + W2 into registers: 272 float4 -> 9 per lane (t=8 half-valid)
    float4 wreg[9], ereg[9];
    const float4* w2 = (const float4*)W2;
    const float4* ae = (const float4*)(g_Aemo + (size_t)(b * L_ + i) * PF);
    #pragma unroll
    for (int t = 0; t < 9; t++) {
        int c4 = t * 32 + lane;
        if (c4 < PF / 4) {
            wreg[t] = w2[c4];
            ereg[t] = ae[c4];
        } else {
            wreg[t] = make_float4(0.f, 0.f, 0.f, 0.f);
            ereg[t] = make_float4(0.f, 0.f, 0.f, 0.f);
        }
    }
    const float bias = __ldg(b2);

    int lo = i - KW; if (lo < 0) lo = 0;
    int hi = i + KW; if (hi > L_ - 1) hi = L_ - 1;
    const int pbase = g_poff[i] - lo;
    const int outb = b * NPAIR;

    for (int jj = lo; jj <= hi; jj++) {
        const float4* ac = (const float4*)(g_Acau + (size_t)(b * L_ + jj) * PF);
        const float4* ap = (const float4*)(g_Apos + (size_t)(jj - i + KW) * PF);

        float sum = 0.f;
        #pragma unroll
        for (int t = 0; t < 9; t++) {
            int c4 = t * 32 + lane;
            if (c4 < PF / 4) {
                float4 c = __ldg(&ac[c4]);
                float4 q = __ldg(&ap[c4]);
                float4 e = ereg[t];
                float4 w = wreg[t];
                float v0 = fmaxf(e.x + c.x + q.x, 0.f);
                float v1 = fmaxf(e.y + c.y + q.y, 0.f);
                float v2 = fmaxf(e.z + c.z + q.z, 0.f);
                float v3 = fmaxf(e.w + c.w + q.w, 0.f);
                sum = fmaf(v0, w.x, sum);
                sum = fmaf(v1, w.y, sum);
                sum = fmaf(v2, w.z, sum);
                sum = fmaf(v3, w.w, sum);
            }
        }
        #pragma unroll
        for (int o = 16; o > 0; o >>= 1)
            sum += __shfl_xor_sync(0xFFFFFFFF, sum, o);
        if (lane == 0) out[outb + pbase + jj] = sum + bias;
    }
}

// ---------------- launch ------------------------------------------------------
extern "C" void kernel_launch(void* const* d_in, const int* in_sizes, int n_in,
                              void* d_out, int out_size) {
    const float* h_emo  = (const float*)d_in[0];
    const float* h_cau  = (const float*)d_in[1];
    const float* pos    = (const float*)d_in[2];
    const float* W1     = (const float*)d_in[3];
    const float* b1     = (const float*)d_in[4];
    const float* W2     = (const float*)d_in[5];
    const float* b2     = (const float*)d_in[6];
    float* out = (float*)d_out;

    const int gemm_smem = NSTAGE * STAGE_ELEMS * (int)sizeof(__nv_bfloat16);
    static bool configured = false;
    if (!configured) {
        cudaFuncSetAttribute(mma_gemm_kernel,
                             cudaFuncAttributeMaxDynamicSharedMemorySize, gemm_smem);
        configured = true;
    }

    init_pairs_kernel<<<1, 128>>>(out, out_size);
    init_f_kernel<<<(NREL * PE + 255) / 256, 256>>>(pos);
    init_apos_kernel<<<(NREL * PF + 255) / 256, 256>>>(W1, b1);
    conv_x_kernel<<<(M_ * GCN / 8 + 255) / 256, 256>>>(h_emo, h_cau);
    conv_w_kernel<<<(PF * GCN / 8 + 255) / 256, 256>>>(W1);

    dim3 ggrid(PFP / BN, M_ / BM, 2);   // (9, 16, 2)
    mma_gemm_kernel<<<ggrid, 256, gemm_smem>>>();

    int warps = B_ * L_;                 // 2048 warps, one per (b, i)
    epilogue_kernel<<<warps * 32 / 256, 256>>>(W2, b2, out);
}

// round 9
// speedup vs baseline: 1.4690x; 1.4690x over previous
#include <cuda_runtime.h>
#include <cuda_bf16.h>
#include <math.h>
#include <stdint.h>

// Problem constants
#define B_   16
#define L_   128
#define KW   8
#define NPAIR 2104
#define GCN  512
#define PE   64
#define PF   1088
#define PFP  1152
#define M_   2048
#define NREL 17
#define NT   48           // k-tiles: 3 segments x 16 tiles of 32

// ---------------- scratch ----------------------------------------------------
__device__ float g_Aemo[M_ * PF];
__device__ float g_Acau[M_ * PF];
__device__ float g_Apos[NREL * PF];
__device__ float g_f[NREL * PE];
__device__ int   g_pi[NPAIR];
__device__ int   g_pj[NPAIR];
__device__ int   g_pr[NPAIR];
__device__ __nv_bfloat16 g_Ahi[2][M_ * GCN];
__device__ __nv_bfloat16 g_Alo[2][M_ * GCN];
__device__ __nv_bfloat16 g_Bhi[2][PFP * GCN];
__device__ __nv_bfloat16 g_Blo[2][PFP * GCN];

// ---------------- init: pair indices + emo_cau_pos tail ----------------------
__global__ void init_pairs_kernel(float* __restrict__ out, int out_size) {
    int i = threadIdx.x;
    if (i >= L_) return;
    int off = 0;
    for (int t = 0; t < i; t++) {
        int lo = t - KW; if (lo < 0) lo = 0;
        int hi = t + KW; if (hi > L_ - 1) hi = L_ - 1;
        off += hi - lo + 1;
    }
    int lo = i - KW; if (lo < 0) lo = 0;
    int hi = i + KW; if (hi > L_ - 1) hi = L_ - 1;
    bool write_pos = (out_size == B_ * NPAIR + 2 * NPAIR);
    for (int j = lo; j <= hi; j++) {
        int p = off + (j - lo);
        g_pi[p] = i;
        g_pj[p] = j;
        g_pr[p] = (j - i) + KW;
        if (write_pos) {
            out[B_ * NPAIR + 2 * p + 0] = (float)(i + 1);
            out[B_ * NPAIR + 2 * p + 1] = (float)(j + 1);
        }
    }
}

// ---------------- init: smoothed positional table f [17 x 64] ----------------
__global__ void init_f_kernel(const float* __restrict__ pos_emb) {
    int idx = blockIdx.x * blockDim.x + threadIdx.x;
    if (idx >= NREL * PE) return;
    int r = idx / PE;
    int e = idx % PE;
    float s = 0.f;
    #pragma unroll
    for (int d = 0; d < NREL; d++) {
        int ad = d - KW; if (ad < 0) ad = -ad;
        float cnt = (float)(L_ - ad);
        int dd = r - d;
        float w = cnt * expf(-(float)(dd * dd));
        s += w * pos_emb[d * PE + e];
    }
    g_f[idx] = s;
}

// ---------------- init: A_pos (includes b1) ----------------------------------
__global__ void init_apos_kernel(const float* __restrict__ W1,
                                 const float* __restrict__ b1) {
    int idx = blockIdx.x * blockDim.x + threadIdx.x;
    if (idx >= NREL * PF) return;
    int r = idx / PF;
    int g = idx % PF;
    float s = b1[g];
    const float* w = W1 + g * PF + 2 * GCN;
    const float* f = g_f + r * PE;
    #pragma unroll 8
    for (int e = 0; e < PE; e++) s += f[e] * w[e];
    g_Apos[idx] = s;
}

// ---------------- convert: X -> hi/lo bf16 (vectorized, R3 version) ----------
__global__ void conv_x_kernel(const float* __restrict__ Xe,
                              const float* __restrict__ Xc) {
    int idx = blockIdx.x * blockDim.x + threadIdx.x;
    if (idx >= M_ * GCN / 4) return;
    #pragma unroll
    for (int z = 0; z < 2; z++) {
        const float* X = z ? Xc : Xe;
        float4 v = *(const float4*)(X + (size_t)idx * 4);
        __nv_bfloat16 h0 = __float2bfloat16(v.x);
        __nv_bfloat16 h1 = __float2bfloat16(v.y);
        __nv_bfloat16 h2 = __float2bfloat16(v.z);
        __nv_bfloat16 h3 = __float2bfloat16(v.w);
        __nv_bfloat162* hp = (__nv_bfloat162*)(&g_Ahi[z][(size_t)idx * 4]);
        hp[0] = __nv_bfloat162(h0, h1);
        hp[1] = __nv_bfloat162(h2, h3);
        __nv_bfloat162* lp = (__nv_bfloat162*)(&g_Alo[z][(size_t)idx * 4]);
        lp[0] = __nv_bfloat162(__float2bfloat16(v.x - __bfloat162float(h0)),
                               __float2bfloat16(v.y - __bfloat162float(h1)));
        lp[1] = __nv_bfloat162(__float2bfloat16(v.z - __bfloat162float(h2)),
                               __float2bfloat16(v.w - __bfloat162float(h3)));
    }
}

// ---------------- convert: W1 -> hi/lo bf16 (vectorized, R3 version) ---------
__global__ void conv_w_kernel(const float* __restrict__ W1) {
    int idx = blockIdx.x * blockDim.x + threadIdx.x;
    if (idx >= PF * GCN / 4) return;
    int g = idx / (GCN / 4), kq = idx % (GCN / 4);
    #pragma unroll
    for (int z = 0; z < 2; z++) {
        float4 v = *(const float4*)(W1 + (size_t)g * PF + z * GCN + kq * 4);
        __nv_bfloat16 h0 = __float2bfloat16(v.x);
        __nv_bfloat16 h1 = __float2bfloat16(v.y);
        __nv_bfloat16 h2 = __float2bfloat16(v.z);
        __nv_bfloat16 h3 = __float2bfloat16(v.w);
        __nv_bfloat162* hp = (__nv_bfloat162*)(&g_Bhi[z][(size_t)g * GCN + kq * 4]);
        hp[0] = __nv_bfloat162(h0, h1);
        hp[1] = __nv_bfloat162(h2, h3);
        __nv_bfloat162* lp = (__nv_bfloat162*)(&g_Blo[z][(size_t)g * GCN + kq * 4]);
        lp[0] = __nv_bfloat162(__float2bfloat16(v.x - __bfloat162float(h0)),
                               __float2bfloat16(v.y - __bfloat162float(h1)));
        lp[1] = __nv_bfloat162(__float2bfloat16(v.z - __bfloat162float(h2)),
                               __float2bfloat16(v.w - __bfloat162float(h3)));
    }
}

// ---------------- bf16 tensor-core GEMM (128x128x32, ldmatrix, 3-stage) ------
#define BM 128
#define BN 128
#define BK 32
#define SSTR 40
#define NSTAGE 3
#define SA_ELEMS (BM * SSTR)
#define SB_ELEMS (BN * SSTR)
#define STAGE_ELEMS (SA_ELEMS + SB_ELEMS)

__device__ __forceinline__ void cp16(void* smem, const void* g) {
    unsigned s = (unsigned)__cvta_generic_to_shared(smem);
    asm volatile("cp.async.cg.shared.global [%0], [%1], 16;\n" :: "r"(s), "l"(g));
}
#define CP_COMMIT() asm volatile("cp.async.commit_group;\n" ::: "memory")
#define CP_WAIT1()  asm volatile("cp.async.wait_group 1;\n" ::: "memory")

__device__ __forceinline__ void ldsm4(unsigned& r0, unsigned& r1,
                                      unsigned& r2, unsigned& r3,
                                      const __nv_bfloat16* p) {
    unsigned a = (unsigned)__cvta_generic_to_shared(p);
    asm volatile("ldmatrix.sync.aligned.m8n8.x4.shared.b16 {%0,%1,%2,%3}, [%4];\n"
                 : "=r"(r0), "=r"(r1), "=r"(r2), "=r"(r3) : "r"(a));
}

extern __shared__ __align__(16) unsigned char dynraw[];

__global__ void __launch_bounds__(256, 2)
mma_gemm_kernel() {
    __nv_bfloat16* dynsmem = (__nv_bfloat16*)dynraw;
    const int z = blockIdx.z;
    const __nv_bfloat16* __restrict__ Ahi = g_Ahi[z];
    const __nv_bfloat16* __restrict__ Alo = g_Alo[z];
    const __nv_bfloat16* __restrict__ Bhi = g_Bhi[z];
    const __nv_bfloat16* __restrict__ Blo = g_Blo[z];
    float* __restrict__ C = z ? g_Acau : g_Aemo;

    const int tid  = threadIdx.x;
    const int lane = tid & 31;
    const int wid  = tid >> 5;
    const int wmBase = (wid & 1) * 64;
    const int wnBase = (wid >> 1) * 32;
    const int m0 = blockIdx.y * BM;
    const int n0 = blockIdx.x * BN;

    const int aRow = (lane & 7) + ((lane >> 3) & 1) * 8;
    const int aK   = (lane >> 4) * 8;
    const int bRow = (lane & 7) + (lane >> 4) * 8;
    const int bK   = ((lane >> 3) & 1) * 8;

    float acc[4][4][4];
    #pragma unroll
    for (int mt = 0; mt < 4; mt++)
        #pragma unroll
        for (int nt = 0; nt < 4; nt++)
            #pragma unroll
            for (int e = 0; e < 4; e++) acc[mt][nt][e] = 0.f;

    auto load_stage = [&](int kt, int s) {
        const int seg = kt >> 4;
        const int kc  = (kt & 15) * BK;
        const __nv_bfloat16* __restrict__ Asrc = (seg < 2) ? Ahi : Alo;
        const __nv_bfloat16* __restrict__ Bsrc = (seg == 1) ? Blo : Bhi;
        __nv_bfloat16* sA = dynsmem + s * STAGE_ELEMS;
        __nv_bfloat16* sB = sA + SA_ELEMS;
        #pragma unroll
        for (int l = 0; l < 2; l++) {
            int q = tid + l * 256;
            int row = q >> 2, c8 = (q & 3) * 8;
            cp16(&sA[row * SSTR + c8],
                 Asrc + (size_t)(m0 + row) * GCN + kc + c8);
        }
        #pragma unroll
        for (int l = 0; l < 2; l++) {
            int q = tid + l * 256;
            int row = q >> 2, c8 = (q & 3) * 8;
            cp16(&sB[row * SSTR + c8],
                 Bsrc + (size_t)(n0 + row) * GCN + kc + c8);
        }
    };

    load_stage(0, 0); CP_COMMIT();
    load_stage(1, 1); CP_COMMIT();

    for (int kt = 0; kt < NT; kt++) {
        CP_WAIT1();
        __syncthreads();
        if (kt + 2 < NT) load_stage(kt + 2, (kt + 2) % NSTAGE);
        CP_COMMIT();

        const int s = kt % NSTAGE;
        const __nv_bfloat16* sA = dynsmem + s * STAGE_ELEMS;
        const __nv_bfloat16* sB = sA + SA_ELEMS;

        #pragma unroll
        for (int kk = 0; kk < BK; kk += 16) {
            unsigned a[4][4], b[2][4];
            #pragma unroll
            for (int mt = 0; mt < 4; mt++)
                ldsm4(a[mt][0], a[mt][1], a[mt][2], a[mt][3],
                      &sA[(wmBase + mt * 16 + aRow) * SSTR + kk + aK]);
            #pragma unroll
            for (int ntp = 0; ntp < 2; ntp++)
                ldsm4(b[ntp][0], b[ntp][1], b[ntp][2], b[ntp][3],
                      &sB[(wnBase + ntp * 16 + bRow) * SSTR + kk + bK]);
            #pragma unroll
            for (int mt = 0; mt < 4; mt++)
                #pragma unroll
                for (int nt = 0; nt < 4; nt++) {
                    unsigned b0 = b[nt >> 1][(nt & 1) * 2];
                    unsigned b1 = b[nt >> 1][(nt & 1) * 2 + 1];
                    asm volatile(
                        "mma.sync.aligned.m16n8k16.row.col.f32.bf16.bf16.f32 "
                        "{%0,%1,%2,%3}, {%4,%5,%6,%7}, {%8,%9}, {%0,%1,%2,%3};\n"
                        : "+f"(acc[mt][nt][0]), "+f"(acc[mt][nt][1]),
                          "+f"(acc[mt][nt][2]), "+f"(acc[mt][nt][3])
                        : "r"(a[mt][0]), "r"(a[mt][1]), "r"(a[mt][2]), "r"(a[mt][3]),
                          "r"(b0), "r"(b1));
                }
        }
    }

    #pragma unroll
    for (int mt = 0; mt < 4; mt++) {
        int row = m0 + wmBase + mt * 16 + (lane >> 2);
        #pragma unroll
        for (int nt = 0; nt < 4; nt++) {
            int col = n0 + wnBase + nt * 8 + (lane & 3) * 2;
            if (col < PF) {
                *(float2*)&C[(size_t)row * PF + col] =
                    make_float2(acc[mt][nt][0], acc[mt][nt][1]);
                *(float2*)&C[(size_t)(row + 8) * PF + col] =
                    make_float2(acc[mt][nt][2], acc[mt][nt][3]);
            }
        }
    }
}

// ---------------- epilogue: 2 pairs per warp, shared-i emo row in regs -------
#define HPAIR (NPAIR / 2)     // 1052

__device__ __forceinline__ float pair_dot(const float4* __restrict__ e9,
                                          const float4* __restrict__ ac,
                                          const float4* __restrict__ ap,
                                          const float4* __restrict__ w2,
                                          int lane) {
    float sum = 0.f;
    #pragma unroll
    for (int t = 0; t < 9; t++) {
        int c4 = t * 32 + lane;
        if (c4 < PF / 4) {
            float4 e = e9[t];
            float4 c = __ldg(&ac[c4]);
            float4 q = __ldg(&ap[c4]);
            float4 w = __ldg(&w2[c4]);
            float v0 = fmaxf(e.x + c.x + q.x, 0.f);
            float v1 = fmaxf(e.y + c.y + q.y, 0.f);
            float v2 = fmaxf(e.z + c.z + q.z, 0.f);
            float v3 = fmaxf(e.w + c.w + q.w, 0.f);
            sum = fmaf(v0, w.x, sum);
            sum = fmaf(v1, w.y, sum);
            sum = fmaf(v2, w.z, sum);
            sum = fmaf(v3, w.w, sum);
        }
    }
    #pragma unroll
    for (int o = 16; o > 0; o >>= 1)
        sum += __shfl_xor_sync(0xFFFFFFFF, sum, o);
    return sum;
}

__global__ void __launch_bounds__(256)
epilogue_kernel(const float* __restrict__ W2, const float* __restrict__ b2,
                float* __restrict__ out) {
    int gw = (blockIdx.x * blockDim.x + threadIdx.x) >> 5;
    int lane = threadIdx.x & 31;
    if (gw >= B_ * HPAIR) return;
    int b = gw / HPAIR;
    int q = gw - b * HPAIR;
    int p0 = q * 2;
    int p1 = p0 + 1;

    int i0 = g_pi[p0], j0 = g_pj[p0], r0 = g_pr[p0];
    int i1 = g_pi[p1], j1 = g_pj[p1], r1 = g_pr[p1];

    const float4* w2 = (const float4*)W2;
    const float4* ac0 = (const float4*)(g_Acau + (size_t)(b * L_ + j0) * PF);
    const float4* ac1 = (const float4*)(g_Acau + (size_t)(b * L_ + j1) * PF);
    const float4* ap0 = (const float4*)(g_Apos + (size_t)r0 * PF);
    const float4* ap1 = (const float4*)(g_Apos + (size_t)r1 * PF);
    const float bias = __ldg(b2);
    const int outb = b * NPAIR;

    // emo row i0 into registers
    float4 ereg[9];
    {
        const float4* ae = (const float4*)(g_Aemo + (size_t)(b * L_ + i0) * PF);
        #pragma unroll
        for (int t = 0; t < 9; t++) {
            int c4 = t * 32 + lane;
            ereg[t] = (c4 < PF / 4) ? ae[c4] : make_float4(0.f, 0.f, 0.f, 0.f);
        }
    }

    if (i1 == i0) {
        // shared-i fast path: one combined loop, 5 load streams
        float s0 = 0.f, s1 = 0.f;
        #pragma unroll
        for (int t = 0; t < 9; t++) {
            int c4 = t * 32 + lane;
            if (c4 < PF / 4) {
                float4 e  = ereg[t];
                float4 c0 = __ldg(&ac0[c4]);
                float4 c1 = __ldg(&ac1[c4]);
                float4 q0 = __ldg(&ap0[c4]);
                float4 q1 = __ldg(&ap1[c4]);
                float4 w  = __ldg(&w2[c4]);
                float a0 = fmaxf(e.x + c0.x + q0.x, 0.f);
                float a1 = fmaxf(e.y + c0.y + q0.y, 0.f);
                float a2 = fmaxf(e.z + c0.z + q0.z, 0.f);
                float a3 = fmaxf(e.w + c0.w + q0.w, 0.f);
                s0 = fmaf(a0, w.x, s0); s0 = fmaf(a1, w.y, s0);
                s0 = fmaf(a2, w.z, s0); s0 = fmaf(a3, w.w, s0);
                float d0 = fmaxf(e.x + c1.x + q1.x, 0.f);
                float d1 = fmaxf(e.y + c1.y + q1.y, 0.f);
                float d2 = fmaxf(e.z + c1.z + q1.z, 0.f);
                float d3 = fmaxf(e.w + c1.w + q1.w, 0.f);
                s1 = fmaf(d0, w.x, s1); s1 = fmaf(d1, w.y, s1);
                s1 = fmaf(d2, w.z, s1); s1 = fmaf(d3, w.w, s1);
            }
        }
        #pragma unroll
        for (int o = 16; o > 0; o >>= 1) {
            s0 += __shfl_xor_sync(0xFFFFFFFF, s0, o);
            s1 += __shfl_xor_sync(0xFFFFFFFF, s1, o);
        }
        if (lane == 0) {
            out[outb + p0] = s0 + bias;
            out[outb + p1] = s1 + bias;
        }
    } else {
        // boundary: two independent passes
        float s0 = pair_dot(ereg, ac0, ap0, w2, lane);
        {
            const float4* ae = (const float4*)(g_Aemo + (size_t)(b * L_ + i1) * PF);
            #pragma unroll
            for (int t = 0; t < 9; t++) {
                int c4 = t * 32 + lane;
                ereg[t] = (c4 < PF / 4) ? ae[c4] : make_float4(0.f, 0.f, 0.f, 0.f);
            }
        }
        float s1 = pair_dot(ereg, ac1, ap1, w2, lane);
        if (lane == 0) {
            out[outb + p0] = s0 + bias;
            out[outb + p1] = s1 + bias;
        }
    }
}

// ---------------- launch ------------------------------------------------------
extern "C" void kernel_launch(void* const* d_in, const int* in_sizes, int n_in,
                              void* d_out, int out_size) {
    const float* h_emo  = (const float*)d_in[0];
    const float* h_cau  = (const float*)d_in[1];
    const float* pos    = (const float*)d_in[2];
    const float* W1     = (const float*)d_in[3];
    const float* b1     = (const float*)d_in[4];
    const float* W2     = (const float*)d_in[5];
    const float* b2     = (const float*)d_in[6];
    float* out = (float*)d_out;

    const int gemm_smem = NSTAGE * STAGE_ELEMS * (int)sizeof(__nv_bfloat16);
    static bool configured = false;
    if (!configured) {
        cudaFuncSetAttribute(mma_gemm_kernel,
                             cudaFuncAttributeMaxDynamicSharedMemorySize, gemm_smem);
        configured = true;
    }

    init_pairs_kernel<<<1, 128>>>(out, out_size);
    init_f_kernel<<<(NREL * PE + 255) / 256, 256>>>(pos);
    init_apos_kernel<<<(NREL * PF + 255) / 256, 256>>>(W1, b1);
    conv_x_kernel<<<(M_ * GCN / 4 + 255) / 256, 256>>>(h_emo, h_cau);
    conv_w_kernel<<<(PF * GCN / 4 + 255) / 256, 256>>>(W1);

    dim3 ggrid(PFP / BN, M_ / BM, 2);   // (9, 16, 2)
    mma_gemm_kernel<<<ggrid, 256, gemm_smem>>>();

    int warps = B_ * HPAIR;              // 16832 warps, 2 pairs each
    int blocks = (warps * 32 + 255) / 256;
    epilogue_kernel<<<blocks, 256>>>(W2, b2, out);
}

// round 11
// speedup vs baseline: 1.4695x; 1.0003x over previous
#include <cuda_runtime.h>
#include <cuda_bf16.h>
#include <math.h>
#include <stdint.h>

// Problem constants
#define B_   16
#define L_   128
#define KW   8
#define NPAIR 2104
#define GCN  512
#define PE   64
#define PF   1088
#define PFP  1152
#define M_   2048
#define NREL 17
#define NT   48           // k-tiles: 3 segments x 16 tiles of 32

// ---------------- scratch ----------------------------------------------------
__device__ float g_Aemo[M_ * PF];
__device__ float g_Acau[M_ * PF];
__device__ float g_Apos[NREL * PF];
__device__ float g_f[NREL * PE];
__device__ int   g_poff[L_];
__device__ __nv_bfloat16 g_Ahi[2][M_ * GCN];
__device__ __nv_bfloat16 g_Alo[2][M_ * GCN];
__device__ __nv_bfloat16 g_Bhi[2][PFP * GCN];
__device__ __nv_bfloat16 g_Blo[2][PFP * GCN];

// ---------------- init: pair offsets + emo_cau_pos tail ----------------------
__global__ void init_pairs_kernel(float* __restrict__ out, int out_size) {
    int i = threadIdx.x;
    if (i >= L_) return;
    int off = 0;
    for (int t = 0; t < i; t++) {
        int lo = t - KW; if (lo < 0) lo = 0;
        int hi = t + KW; if (hi > L_ - 1) hi = L_ - 1;
        off += hi - lo + 1;
    }
    g_poff[i] = off;
    int lo = i - KW; if (lo < 0) lo = 0;
    int hi = i + KW; if (hi > L_ - 1) hi = L_ - 1;
    if (out_size == B_ * NPAIR + 2 * NPAIR) {
        for (int j = lo; j <= hi; j++) {
            int p = off + (j - lo);
            out[B_ * NPAIR + 2 * p + 0] = (float)(i + 1);
            out[B_ * NPAIR + 2 * p + 1] = (float)(j + 1);
        }
    }
}

// ---------------- init: smoothed positional table f [17 x 64] ----------------
__global__ void init_f_kernel(const float* __restrict__ pos_emb) {
    int idx = blockIdx.x * blockDim.x + threadIdx.x;
    if (idx >= NREL * PE) return;
    int r = idx / PE;
    int e = idx % PE;
    float s = 0.f;
    #pragma unroll
    for (int d = 0; d < NREL; d++) {
        int ad = d - KW; if (ad < 0) ad = -ad;
        float cnt = (float)(L_ - ad);
        int dd = r - d;
        float w = cnt * expf(-(float)(dd * dd));
        s += w * pos_emb[d * PE + e];
    }
    g_f[idx] = s;
}

// ---------------- init: A_pos (includes b1) ----------------------------------
__global__ void init_apos_kernel(const float* __restrict__ W1,
                                 const float* __restrict__ b1) {
    int idx = blockIdx.x * blockDim.x + threadIdx.x;
    if (idx >= NREL * PF) return;
    int r = idx / PF;
    int g = idx % PF;
    float s = b1[g];
    const float* w = W1 + g * PF + 2 * GCN;
    const float* f = g_f + r * PE;
    #pragma unroll 8
    for (int e = 0; e < PE; e++) s += f[e] * w[e];
    g_Apos[idx] = s;
}

// ---------------- convert: X -> hi/lo bf16 (vectorized) ----------------------
__global__ void conv_x_kernel(const float* __restrict__ Xe,
                              const float* __restrict__ Xc) {
    int idx = blockIdx.x * blockDim.x + threadIdx.x;
    if (idx >= M_ * GCN / 4) return;
    #pragma unroll
    for (int z = 0; z < 2; z++) {
        const float* X = z ? Xc : Xe;
        float4 v = *(const float4*)(X + (size_t)idx * 4);
        __nv_bfloat16 h0 = __float2bfloat16(v.x);
        __nv_bfloat16 h1 = __float2bfloat16(v.y);
        __nv_bfloat16 h2 = __float2bfloat16(v.z);
        __nv_bfloat16 h3 = __float2bfloat16(v.w);
        __nv_bfloat162* hp = (__nv_bfloat162*)(&g_Ahi[z][(size_t)idx * 4]);
        hp[0] = __nv_bfloat162(h0, h1);
        hp[1] = __nv_bfloat162(h2, h3);
        __nv_bfloat162* lp = (__nv_bfloat162*)(&g_Alo[z][(size_t)idx * 4]);
        lp[0] = __nv_bfloat162(__float2bfloat16(v.x - __bfloat162float(h0)),
                               __float2bfloat16(v.y - __bfloat162float(h1)));
        lp[1] = __nv_bfloat162(__float2bfloat16(v.z - __bfloat162float(h2)),
                               __float2bfloat16(v.w - __bfloat162float(h3)));
    }
}

// ---------------- convert: W1 -> hi/lo bf16 (vectorized) ---------------------
__global__ void conv_w_kernel(const float* __restrict__ W1) {
    int idx = blockIdx.x * blockDim.x + threadIdx.x;
    if (idx >= PF * GCN / 4) return;
    int g = idx / (GCN / 4), kq = idx % (GCN / 4);
    #pragma unroll
    for (int z = 0; z < 2; z++) {
        float4 v = *(const float4*)(W1 + (size_t)g * PF + z * GCN + kq * 4);
        __nv_bfloat16 h0 = __float2bfloat16(v.x);
        __nv_bfloat16 h1 = __float2bfloat16(v.y);
        __nv_bfloat16 h2 = __float2bfloat16(v.z);
        __nv_bfloat16 h3 = __float2bfloat16(v.w);
        __nv_bfloat162* hp = (__nv_bfloat162*)(&g_Bhi[z][(size_t)g * GCN + kq * 4]);
        hp[0] = __nv_bfloat162(h0, h1);
        hp[1] = __nv_bfloat162(h2, h3);
        __nv_bfloat162* lp = (__nv_bfloat162*)(&g_Blo[z][(size_t)g * GCN + kq * 4]);
        lp[0] = __nv_bfloat162(__float2bfloat16(v.x - __bfloat162float(h0)),
                               __float2bfloat16(v.y - __bfloat162float(h1)));
        lp[1] = __nv_bfloat162(__float2bfloat16(v.z - __bfloat162float(h2)),
                               __float2bfloat16(v.w - __bfloat162float(h3)));
    }
}

// ---------------- bf16 tensor-core GEMM (128x128x32, ldmatrix, 3-stage) ------
#define BM 128
#define BN 128
#define BK 32
#define SSTR 40
#define NSTAGE 3
#define SA_ELEMS (BM * SSTR)
#define SB_ELEMS (BN * SSTR)
#define STAGE_ELEMS (SA_ELEMS + SB_ELEMS)

__device__ __forceinline__ void cp16(void* smem, const void* g) {
    unsigned s = (unsigned)__cvta_generic_to_shared(smem);
    asm volatile("cp.async.cg.shared.global [%0], [%1], 16;\n" :: "r"(s), "l"(g));
}
#define CP_COMMIT() asm volatile("cp.async.commit_group;\n" ::: "memory")
#define CP_WAIT1()  asm volatile("cp.async.wait_group 1;\n" ::: "memory")

__device__ __forceinline__ void ldsm4(unsigned& r0, unsigned& r1,
                                      unsigned& r2, unsigned& r3,
                                      const __nv_bfloat16* p) {
    unsigned a = (unsigned)__cvta_generic_to_shared(p);
    asm volatile("ldmatrix.sync.aligned.m8n8.x4.shared.b16 {%0,%1,%2,%3}, [%4];\n"
                 : "=r"(r0), "=r"(r1), "=r"(r2), "=r"(r3) : "r"(a));
}

extern __shared__ __align__(16) unsigned char dynraw[];

__global__ void __launch_bounds__(256, 2)
mma_gemm_kernel() {
    __nv_bfloat16* dynsmem = (__nv_bfloat16*)dynraw;
    const int z = blockIdx.z;
    const __nv_bfloat16* __restrict__ Ahi = g_Ahi[z];
    const __nv_bfloat16* __restrict__ Alo = g_Alo[z];
    const __nv_bfloat16* __restrict__ Bhi = g_Bhi[z];
    const __nv_bfloat16* __restrict__ Blo = g_Blo[z];
    float* __restrict__ C = z ? g_Acau : g_Aemo;

    const int tid  = threadIdx.x;
    const int lane = tid & 31;
    const int wid  = tid >> 5;
    const int wmBase = (wid & 1) * 64;
    const int wnBase = (wid >> 1) * 32;
    const int m0 = blockIdx.y * BM;
    const int n0 = blockIdx.x * BN;

    const int aRow = (lane & 7) + ((lane >> 3) & 1) * 8;
    const int aK   = (lane >> 4) * 8;
    const int bRow = (lane & 7) + (lane >> 4) * 8;
    const int bK   = ((lane >> 3) & 1) * 8;

    float acc[4][4][4];
    #pragma unroll
    for (int mt = 0; mt < 4; mt++)
        #pragma unroll
        for (int nt = 0; nt < 4; nt++)
            #pragma unroll
            for (int e = 0; e < 4; e++) acc[mt][nt][e] = 0.f;

    auto load_stage = [&](int kt, int s) {
        const int seg = kt >> 4;
        const int kc  = (kt & 15) * BK;
        const __nv_bfloat16* __restrict__ Asrc = (seg < 2) ? Ahi : Alo;
        const __nv_bfloat16* __restrict__ Bsrc = (seg == 1) ? Blo : Bhi;
        __nv_bfloat16* sA = dynsmem + s * STAGE_ELEMS;
        __nv_bfloat16* sB = sA + SA_ELEMS;
        #pragma unroll
        for (int l = 0; l < 2; l++) {
            int q = tid + l * 256;
            int row = q >> 2, c8 = (q & 3) * 8;
            cp16(&sA[row * SSTR + c8],
                 Asrc + (size_t)(m0 + row) * GCN + kc + c8);
        }
        #pragma unroll
        for (int l = 0; l < 2; l++) {
            int q = tid + l * 256;
            int row = q >> 2, c8 = (q & 3) * 8;
            cp16(&sB[row * SSTR + c8],
                 Bsrc + (size_t)(n0 + row) * GCN + kc + c8);
        }
    };

    load_stage(0, 0); CP_COMMIT();
    load_stage(1, 1); CP_COMMIT();

    for (int kt = 0; kt < NT; kt++) {
        CP_WAIT1();
        __syncthreads();
        if (kt + 2 < NT) load_stage(kt + 2, (kt + 2) % NSTAGE);
        CP_COMMIT();

        const int s = kt % NSTAGE;
        const __nv_bfloat16* sA = dynsmem + s * STAGE_ELEMS;
        const __nv_bfloat16* sB = sA + SA_ELEMS;

        #pragma unroll
        for (int kk = 0; kk < BK; kk += 16) {
            unsigned a[4][4], b[2][4];
            #pragma unroll
            for (int mt = 0; mt < 4; mt++)
                ldsm4(a[mt][0], a[mt][1], a[mt][2], a[mt][3],
                      &sA[(wmBase + mt * 16 + aRow) * SSTR + kk + aK]);
            #pragma unroll
            for (int ntp = 0; ntp < 2; ntp++)
                ldsm4(b[ntp][0], b[ntp][1], b[ntp][2], b[ntp][3],
                      &sB[(wnBase + ntp * 16 + bRow) * SSTR + kk + bK]);
            #pragma unroll
            for (int mt = 0; mt < 4; mt++)
                #pragma unroll
                for (int nt = 0; nt < 4; nt++) {
                    unsigned b0 = b[nt >> 1][(nt & 1) * 2];
                    unsigned b1 = b[nt >> 1][(nt & 1) * 2 + 1];
                    asm volatile(
                        "mma.sync.aligned.m16n8k16.row.col.f32.bf16.bf16.f32 "
                        "{%0,%1,%2,%3}, {%4,%5,%6,%7}, {%8,%9}, {%0,%1,%2,%3};\n"
                        : "+f"(acc[mt][nt][0]), "+f"(acc[mt][nt][1]),
                          "+f"(acc[mt][nt][2]), "+f"(acc[mt][nt][3])
                        : "r"(a[mt][0]), "r"(a[mt][1]), "r"(a[mt][2]), "r"(a[mt][3]),
                          "r"(b0), "r"(b1));
                }
        }
    }

    #pragma unroll
    for (int mt = 0; mt < 4; mt++) {
        int row = m0 + wmBase + mt * 16 + (lane >> 2);
        #pragma unroll
        for (int nt = 0; nt < 4; nt++) {
            int col = n0 + wnBase + nt * 8 + (lane & 3) * 2;
            if (col < PF) {
                *(float2*)&C[(size_t)row * PF + col] =
                    make_float2(acc[mt][nt][0], acc[mt][nt][1]);
                *(float2*)&C[(size_t)(row + 8) * PF + col] =
                    make_float2(acc[mt][nt][2], acc[mt][nt][3]);
            }
        }
    }
}

// ---------------- epilogue: warp per (b, i, j-block of 4); W2 in smem --------
#define WPI 5                       // warps per i-row (ceil(17/4))
#define TOTW (B_ * L_ * WPI)        // 10240 warps

__global__ void __launch_bounds__(256)
epilogue_kernel(const float* __restrict__ W2, const float* __restrict__ b2,
                float* __restrict__ out) {
    __shared__ __align__(16) float sW[PF];

    const int tid  = threadIdx.x;
    const int lane = tid & 31;
    const int wid  = tid >> 5;

    // stage W2 into smem
    {
        const float4* src = (const float4*)W2;
        float4* dst = (float4*)sW;
        for (int q = tid; q < PF / 4; q += 256) dst[q] = src[q];
    }
    __syncthreads();

    int gw = blockIdx.x * 8 + wid;
    if (gw >= TOTW) return;
    int b   = gw / (L_ * WPI);
    int rem = gw - b * (L_ * WPI);
    int i   = rem / WPI;
    int k   = rem - i * WPI;

    int lo = i - KW; if (lo < 0) lo = 0;
    int hi = i + KW; if (hi > L_ - 1) hi = L_ - 1;
    int jstart = lo + 4 * k;
    if (jstart > hi) return;
    int cnt = hi - jstart + 1; if (cnt > 4) cnt = 4;

    int js0 = jstart;
    int js1 = jstart + 1 > hi ? hi : jstart + 1;
    int js2 = jstart + 2 > hi ? hi : jstart + 2;
    int js3 = jstart + 3 > hi ? hi : jstart + 3;

    const float4* ac0 = (const float4*)(g_Acau + (size_t)(b * L_ + js0) * PF);
    const float4* ac1 = (const float4*)(g_Acau + (size_t)(b * L_ + js1) * PF);
    const float4* ac2 = (const float4*)(g_Acau + (size_t)(b * L_ + js2) * PF);
    const float4* ac3 = (const float4*)(g_Acau + (size_t)(b * L_ + js3) * PF);
    const float4* ap0 = (const float4*)(g_Apos + (size_t)(js0 - i + KW) * PF);
    const float4* ap1 = (const float4*)(g_Apos + (size_t)(js1 - i + KW) * PF);
    const float4* ap2 = (const float4*)(g_Apos + (size_t)(js2 - i + KW) * PF);
    const float4* ap3 = (const float4*)(g_Apos + (size_t)(js3 - i + KW) * PF);

    // emo row into registers (coalesced per t)
    float4 ereg[9];
    {
        const float4* ae = (const float4*)(g_Aemo + (size_t)(b * L_ + i) * PF);
        #pragma unroll
        for (int t = 0; t < 9; t++) {
            int c4 = t * 32 + lane;
            ereg[t] = (c4 < PF / 4) ? ae[c4] : make_float4(0.f, 0.f, 0.f, 0.f);
        }
    }
    const float bias = __ldg(b2);

    float s0 = 0.f, s1 = 0.f, s2 = 0.f, s3 = 0.f;
    #pragma unroll
    for (int t = 0; t < 9; t++) {
        int c4 = t * 32 + lane;
        if (c4 < PF / 4) {
            float4 e = ereg[t];
            float4 w = ((const float4*)sW)[c4];
            {
                float4 c = __ldg(&ac0[c4]); float4 q = __ldg(&ap0[c4]);
                s0 = fmaf(fmaxf(e.x + c.x + q.x, 0.f), w.x, s0);
                s0 = fmaf(fmaxf(e.y + c.y + q.y, 0.f), w.y, s0);
                s0 = fmaf(fmaxf(e.z + c.z + q.z, 0.f), w.z, s0);
                s0 = fmaf(fmaxf(e.w + c.w + q.w, 0.f), w.w, s0);
            }
            {
                float4 c = __ldg(&ac1[c4]); float4 q = __ldg(&ap1[c4]);
                s1 = fmaf(fmaxf(e.x + c.x + q.x, 0.f), w.x, s1);
                s1 = fmaf(fmaxf(e.y + c.y + q.y, 0.f), w.y, s1);
                s1 = fmaf(fmaxf(e.z + c.z + q.z, 0.f), w.z, s1);
                s1 = fmaf(fmaxf(e.w + c.w + q.w, 0.f), w.w, s1);
            }
            {
                float4 c = __ldg(&ac2[c4]); float4 q = __ldg(&ap2[c4]);
                s2 = fmaf(fmaxf(e.x + c.x + q.x, 0.f), w.x, s2);
                s2 = fmaf(fmaxf(e.y + c.y + q.y, 0.f), w.y, s2);
                s2 = fmaf(fmaxf(e.z + c.z + q.z, 0.f), w.z, s2);
                s2 = fmaf(fmaxf(e.w + c.w + q.w, 0.f), w.w, s2);
            }
            {
                float4 c = __ldg(&ac3[c4]); float4 q = __ldg(&ap3[c4]);
                s3 = fmaf(fmaxf(e.x + c.x + q.x, 0.f), w.x, s3);
                s3 = fmaf(fmaxf(e.y + c.y + q.y, 0.f), w.y, s3);
                s3 = fmaf(fmaxf(e.z + c.z + q.z, 0.f), w.z, s3);
                s3 = fmaf(fmaxf(e.w + c.w + q.w, 0.f), w.w, s3);
            }
        }
    }
    #pragma unroll
    for (int o = 16; o > 0; o >>= 1) {
        s0 += __shfl_xor_sync(0xFFFFFFFF, s0, o);
        s1 += __shfl_xor_sync(0xFFFFFFFF, s1, o);
        s2 += __shfl_xor_sync(0xFFFFFFFF, s2, o);
        s3 += __shfl_xor_sync(0xFFFFFFFF, s3, o);
    }
    if (lane == 0) {
        int pb = b * NPAIR + g_poff[i] + (jstart - lo);
        out[pb] = s0 + bias;
        if (cnt > 1) out[pb + 1] = s1 + bias;
        if (cnt > 2) out[pb + 2] = s2 + bias;
        if (cnt > 3) out[pb + 3] = s3 + bias;
    }
}

// ---------------- launch ------------------------------------------------------
extern "C" void kernel_launch(void* const* d_in, const int* in_sizes, int n_in,
                              void* d_out, int out_size) {
    const float* h_emo  = (const float*)d_in[0];
    const float* h_cau  = (const float*)d_in[1];
    const float* pos    = (const float*)d_in[2];
    const float* W1     = (const float*)d_in[3];
    const float* b1     = (const float*)d_in[4];
    const float* W2     = (const float*)d_in[5];
    const float* b2     = (const float*)d_in[6];
    float* out = (float*)d_out;

    const int gemm_smem = NSTAGE * STAGE_ELEMS * (int)sizeof(__nv_bfloat16);
    static bool configured = false;
    if (!configured) {
        cudaFuncSetAttribute(mma_gemm_kernel,
                             cudaFuncAttributeMaxDynamicSharedMemorySize, gemm_smem);
        configured = true;
    }

    init_pairs_kernel<<<1, 128>>>(out, out_size);
    init_f_kernel<<<(NREL * PE + 255) / 256, 256>>>(pos);
    init_apos_kernel<<<(NREL * PF + 255) / 256, 256>>>(W1, b1);
    conv_x_kernel<<<(M_ * GCN / 4 + 255) / 256, 256>>>(h_emo, h_cau);
    conv_w_kernel<<<(PF * GCN / 4 + 255) / 256, 256>>>(W1);

    dim3 ggrid(PFP / BN, M_ / BM, 2);   // (9, 16, 2)
    mma_gemm_kernel<<<ggrid, 256, gemm_smem>>>();

    int blocks = (TOTW * 32 + 255) / 256;   // 1280 blocks
    epilogue_kernel<<<blocks, 256>>>(W2, b2, out);
}

// round 13
// speedup vs baseline: 1.5185x; 1.0334x over previous
#include <cuda_runtime.h>
#include <cuda_bf16.h>
#include <math.h>
#include <stdint.h>

// Problem constants
#define B_   16
#define L_   128
#define KW   8
#define NPAIR 2104
#define GCN  512
#define PE   64
#define PF   1088
#define PFP  1152
#define M_   2048
#define NREL 17
#define NT   48           // k-tiles: 3 segments x 16 tiles of 32

// ---------------- scratch ----------------------------------------------------
__device__ float g_Aemo[M_ * PF];
__device__ float g_Acau[M_ * PF];
__device__ float g_Apos[NREL * PF];
__device__ float g_f[NREL * PE];
__device__ int   g_poff[L_];
__device__ __nv_bfloat16 g_Ahi[2][M_ * GCN];
__device__ __nv_bfloat16 g_Alo[2][M_ * GCN];
__device__ __nv_bfloat16 g_Bhi[2][PFP * GCN];
__device__ __nv_bfloat16 g_Blo[2][PFP * GCN];

// ---------------- init: pair offsets + emo_cau_pos tail ----------------------
__global__ void init_pairs_kernel(float* __restrict__ out, int out_size) {
    int i = threadIdx.x;
    if (i >= L_) return;
    int off = 0;
    for (int t = 0; t < i; t++) {
        int lo = t - KW; if (lo < 0) lo = 0;
        int hi = t + KW; if (hi > L_ - 1) hi = L_ - 1;
        off += hi - lo + 1;
    }
    g_poff[i] = off;
    int lo = i - KW; if (lo < 0) lo = 0;
    int hi = i + KW; if (hi > L_ - 1) hi = L_ - 1;
    if (out_size == B_ * NPAIR + 2 * NPAIR) {
        for (int j = lo; j <= hi; j++) {
            int p = off + (j - lo);
            out[B_ * NPAIR + 2 * p + 0] = (float)(i + 1);
            out[B_ * NPAIR + 2 * p + 1] = (float)(j + 1);
        }
    }
}

// ---------------- init: smoothed positional table f [17 x 64] ----------------
__global__ void init_f_kernel(const float* __restrict__ pos_emb) {
    int idx = blockIdx.x * blockDim.x + threadIdx.x;
    if (idx >= NREL * PE) return;
    int r = idx / PE;
    int e = idx % PE;
    float s = 0.f;
    #pragma unroll
    for (int d = 0; d < NREL; d++) {
        int ad = d - KW; if (ad < 0) ad = -ad;
        float cnt = (float)(L_ - ad);
        int dd = r - d;
        float w = cnt * expf(-(float)(dd * dd));
        s += w * pos_emb[d * PE + e];
    }
    g_f[idx] = s;
}

// ---------------- init: A_pos (includes b1) ----------------------------------
__global__ void init_apos_kernel(const float* __restrict__ W1,
                                 const float* __restrict__ b1) {
    int idx = blockIdx.x * blockDim.x + threadIdx.x;
    if (idx >= NREL * PF) return;
    int r = idx / PF;
    int g = idx % PF;
    float s = b1[g];
    const float* w = W1 + g * PF + 2 * GCN;
    const float* f = g_f + r * PE;
    #pragma unroll 8
    for (int e = 0; e < PE; e++) s += f[e] * w[e];
    g_Apos[idx] = s;
}

// ---------------- merged convert: X and W1 -> hi/lo bf16 ---------------------
#define XBLK (M_ * GCN / 4 / 256)        // 1024 blocks for X portion
#define WBLK (PF * GCN / 4 / 256)        // 1088 blocks for W portion

__global__ void conv_all_kernel(const float* __restrict__ Xe,
                                const float* __restrict__ Xc,
                                const float* __restrict__ W1) {
    int blk = blockIdx.x;
    if (blk < XBLK) {
        int idx = blk * 256 + threadIdx.x;
        #pragma unroll
        for (int z = 0; z < 2; z++) {
            const float* X = z ? Xc : Xe;
            float4 v = *(const float4*)(X + (size_t)idx * 4);
            __nv_bfloat16 h0 = __float2bfloat16(v.x);
            __nv_bfloat16 h1 = __float2bfloat16(v.y);
            __nv_bfloat16 h2 = __float2bfloat16(v.z);
            __nv_bfloat16 h3 = __float2bfloat16(v.w);
            __nv_bfloat162* hp = (__nv_bfloat162*)(&g_Ahi[z][(size_t)idx * 4]);
            hp[0] = __nv_bfloat162(h0, h1);
            hp[1] = __nv_bfloat162(h2, h3);
            __nv_bfloat162* lp = (__nv_bfloat162*)(&g_Alo[z][(size_t)idx * 4]);
            lp[0] = __nv_bfloat162(__float2bfloat16(v.x - __bfloat162float(h0)),
                                   __float2bfloat16(v.y - __bfloat162float(h1)));
            lp[1] = __nv_bfloat162(__float2bfloat16(v.z - __bfloat162float(h2)),
                                   __float2bfloat16(v.w - __bfloat162float(h3)));
        }
    } else {
        int idx = (blk - XBLK) * 256 + threadIdx.x;
        int g = idx / (GCN / 4), kq = idx % (GCN / 4);
        #pragma unroll
        for (int z = 0; z < 2; z++) {
            float4 v = *(const float4*)(W1 + (size_t)g * PF + z * GCN + kq * 4);
            __nv_bfloat16 h0 = __float2bfloat16(v.x);
            __nv_bfloat16 h1 = __float2bfloat16(v.y);
            __nv_bfloat16 h2 = __float2bfloat16(v.z);
            __nv_bfloat16 h3 = __float2bfloat16(v.w);
            __nv_bfloat162* hp = (__nv_bfloat162*)(&g_Bhi[z][(size_t)g * GCN + kq * 4]);
            hp[0] = __nv_bfloat162(h0, h1);
            hp[1] = __nv_bfloat162(h2, h3);
            __nv_bfloat162* lp = (__nv_bfloat162*)(&g_Blo[z][(size_t)g * GCN + kq * 4]);
            lp[0] = __nv_bfloat162(__float2bfloat16(v.x - __bfloat162float(h0)),
                                   __float2bfloat16(v.y - __bfloat162float(h1)));
            lp[1] = __nv_bfloat162(__float2bfloat16(v.z - __bfloat162float(h2)),
                                   __float2bfloat16(v.w - __bfloat162float(h3)));
        }
    }
}

// ---------------- bf16 tensor-core GEMM (128x128x32, ldmatrix, 3-stage) ------
#define BM 128
#define BN 128
#define BK 32
#define SSTR 40
#define NSTAGE 3
#define SA_ELEMS (BM * SSTR)
#define SB_ELEMS (BN * SSTR)
#define STAGE_ELEMS (SA_ELEMS + SB_ELEMS)

__device__ __forceinline__ void cp16(void* smem, const void* g) {
    unsigned s = (unsigned)__cvta_generic_to_shared(smem);
    asm volatile("cp.async.cg.shared.global [%0], [%1], 16;\n" :: "r"(s), "l"(g));
}
#define CP_COMMIT() asm volatile("cp.async.commit_group;\n" ::: "memory")
#define CP_WAIT1()  asm volatile("cp.async.wait_group 1;\n" ::: "memory")

__device__ __forceinline__ void ldsm4(unsigned& r0, unsigned& r1,
                                      unsigned& r2, unsigned& r3,
                                      const __nv_bfloat16* p) {
    unsigned a = (unsigned)__cvta_generic_to_shared(p);
    asm volatile("ldmatrix.sync.aligned.m8n8.x4.shared.b16 {%0,%1,%2,%3}, [%4];\n"
                 : "=r"(r0), "=r"(r1), "=r"(r2), "=r"(r3) : "r"(a));
}

extern __shared__ __align__(16) unsigned char dynraw[];

__global__ void __launch_bounds__(256, 2)
mma_gemm_kernel() {
    __nv_bfloat16* dynsmem = (__nv_bfloat16*)dynraw;
    const int z = blockIdx.z;
    const __nv_bfloat16* __restrict__ Ahi = g_Ahi[z];
    const __nv_bfloat16* __restrict__ Alo = g_Alo[z];
    const __nv_bfloat16* __restrict__ Bhi = g_Bhi[z];
    const __nv_bfloat16* __restrict__ Blo = g_Blo[z];
    float* __restrict__ C = z ? g_Acau : g_Aemo;

    const int tid  = threadIdx.x;
    const int lane = tid & 31;
    const int wid  = tid >> 5;
    const int wmBase = (wid & 1) * 64;
    const int wnBase = (wid >> 1) * 32;
    const int m0 = blockIdx.y * BM;
    const int n0 = blockIdx.x * BN;

    const int aRow = (lane & 7) + ((lane >> 3) & 1) * 8;
    const int aK   = (lane >> 4) * 8;
    const int bRow = (lane & 7) + (lane >> 4) * 8;
    const int bK   = ((lane >> 3) & 1) * 8;

    float acc[4][4][4];
    #pragma unroll
    for (int mt = 0; mt < 4; mt++)
        #pragma unroll
        for (int nt = 0; nt < 4; nt++)
            #pragma unroll
            for (int e = 0; e < 4; e++) acc[mt][nt][e] = 0.f;

    auto load_stage = [&](int kt, int s) {
        const int seg = kt >> 4;
        const int kc  = (kt & 15) * BK;
        const __nv_bfloat16* __restrict__ Asrc = (seg < 2) ? Ahi : Alo;
        const __nv_bfloat16* __restrict__ Bsrc = (seg == 1) ? Blo : Bhi;
        __nv_bfloat16* sA = dynsmem + s * STAGE_ELEMS;
        __nv_bfloat16* sB = sA + SA_ELEMS;
        #pragma unroll
        for (int l = 0; l < 2; l++) {
            int q = tid + l * 256;
            int row = q >> 2, c8 = (q & 3) * 8;
            cp16(&sA[row * SSTR + c8],
                 Asrc + (size_t)(m0 + row) * GCN + kc + c8);
        }
        #pragma unroll
        for (int l = 0; l < 2; l++) {
            int q = tid + l * 256;
            int row = q >> 2, c8 = (q & 3) * 8;
            cp16(&sB[row * SSTR + c8],
                 Bsrc + (size_t)(n0 + row) * GCN + kc + c8);
        }
    };

    load_stage(0, 0); CP_COMMIT();
    load_stage(1, 1); CP_COMMIT();

    for (int kt = 0; kt < NT; kt++) {
        CP_WAIT1();
        __syncthreads();
        if (kt + 2 < NT) load_stage(kt + 2, (kt + 2) % NSTAGE);
        CP_COMMIT();

        const int s = kt % NSTAGE;
        const __nv_bfloat16* sA = dynsmem + s * STAGE_ELEMS;
        const __nv_bfloat16* sB = sA + SA_ELEMS;

        #pragma unroll
        for (int kk = 0; kk < BK; kk += 16) {
            unsigned a[4][4], b[2][4];
            #pragma unroll
            for (int mt = 0; mt < 4; mt++)
                ldsm4(a[mt][0], a[mt][1], a[mt][2], a[mt][3],
                      &sA[(wmBase + mt * 16 + aRow) * SSTR + kk + aK]);
            #pragma unroll
            for (int ntp = 0; ntp < 2; ntp++)
                ldsm4(b[ntp][0], b[ntp][1], b[ntp][2], b[ntp][3],
                      &sB[(wnBase + ntp * 16 + bRow) * SSTR + kk + bK]);
            #pragma unroll
            for (int mt = 0; mt < 4; mt++)
                #pragma unroll
                for (int nt = 0; nt < 4; nt++) {
                    unsigned b0 = b[nt >> 1][(nt & 1) * 2];
                    unsigned b1 = b[nt >> 1][(nt & 1) * 2 + 1];
                    asm volatile(
                        "mma.sync.aligned.m16n8k16.row.col.f32.bf16.bf16.f32 "
                        "{%0,%1,%2,%3}, {%4,%5,%6,%7}, {%8,%9}, {%0,%1,%2,%3};\n"
                        : "+f"(acc[mt][nt][0]), "+f"(acc[mt][nt][1]),
                          "+f"(acc[mt][nt][2]), "+f"(acc[mt][nt][3])
                        : "r"(a[mt][0]), "r"(a[mt][1]), "r"(a[mt][2]), "r"(a[mt][3]),
                          "r"(b0), "r"(b1));
                }
        }
    }

    #pragma unroll
    for (int mt = 0; mt < 4; mt++) {
        int row = m0 + wmBase + mt * 16 + (lane >> 2);
        #pragma unroll
        for (int nt = 0; nt < 4; nt++) {
            int col = n0 + wnBase + nt * 8 + (lane & 3) * 2;
            if (col < PF) {
                *(float2*)&C[(size_t)row * PF + col] =
                    make_float2(acc[mt][nt][0], acc[mt][nt][1]);
                *(float2*)&C[(size_t)(row + 8) * PF + col] =
                    make_float2(acc[mt][nt][2], acc[mt][nt][3]);
            }
        }
    }
}

// ---------------- packed f32x2 helpers ---------------------------------------
__device__ __forceinline__ unsigned long long f2add(unsigned long long a,
                                                    unsigned long long b) {
    unsigned long long r;
    asm("add.rn.f32x2 %0, %1, %2;" : "=l"(r) : "l"(a), "l"(b));
    return r;
}
__device__ __forceinline__ unsigned long long f2fma(unsigned long long a,
                                                    unsigned long long b,
                                                    unsigned long long c) {
    unsigned long long r;
    asm("fma.rn.f32x2 %0, %1, %2, %3;" : "=l"(r) : "l"(a), "l"(b), "l"(c));
    return r;
}
__device__ __forceinline__ unsigned long long f2relu(unsigned long long v) {
    float lo, hi;
    asm("mov.b64 {%0,%1}, %2;" : "=f"(lo), "=f"(hi) : "l"(v));
    lo = fmaxf(lo, 0.f);
    hi = fmaxf(hi, 0.f);
    unsigned long long r;
    asm("mov.b64 %0, {%1,%2};" : "=l"(r) : "f"(lo), "f"(hi));
    return r;
}
__device__ __forceinline__ float f2sum(unsigned long long v) {
    float lo, hi;
    asm("mov.b64 {%0,%1}, %2;" : "=f"(lo), "=f"(hi) : "l"(v));
    return lo + hi;
}

// ---------------- epilogue: warp/(b,i,4j), packed f32x2, W2 in smem ----------
#define WPI 5
#define TOTW (B_ * L_ * WPI)

__global__ void __launch_bounds__(256)
epilogue_kernel(const float* __restrict__ W2, const float* __restrict__ b2,
                float* __restrict__ out) {
    __shared__ __align__(16) float sW[PF];

    const int tid  = threadIdx.x;
    const int lane = tid & 31;
    const int wid  = tid >> 5;

    {
        const float4* src = (const float4*)W2;
        float4* dst = (float4*)sW;
        for (int q = tid; q < PF / 4; q += 256) dst[q] = src[q];
    }
    __syncthreads();

    int gw = blockIdx.x * 8 + wid;
    if (gw >= TOTW) return;
    int b   = gw / (L_ * WPI);
    int rem = gw - b * (L_ * WPI);
    int i   = rem / WPI;
    int k   = rem - i * WPI;

    int lo = i - KW; if (lo < 0) lo = 0;
    int hi = i + KW; if (hi > L_ - 1) hi = L_ - 1;
    int jstart = lo + 4 * k;
    if (jstart > hi) return;
    int cnt = hi - jstart + 1; if (cnt > 4) cnt = 4;

    int js0 = jstart;
    int js1 = jstart + 1 > hi ? hi : jstart + 1;
    int js2 = jstart + 2 > hi ? hi : jstart + 2;
    int js3 = jstart + 3 > hi ? hi : jstart + 3;

    const ulonglong2* __restrict__ ac0 =
        (const ulonglong2*)(g_Acau + (size_t)(b * L_ + js0) * PF);
    const ulonglong2* __restrict__ ac1 =
        (const ulonglong2*)(g_Acau + (size_t)(b * L_ + js1) * PF);
    const ulonglong2* __restrict__ ac2 =
        (const ulonglong2*)(g_Acau + (size_t)(b * L_ + js2) * PF);
    const ulonglong2* __restrict__ ac3 =
        (const ulonglong2*)(g_Acau + (size_t)(b * L_ + js3) * PF);
    const ulonglong2* __restrict__ ap0 =
        (const ulonglong2*)(g_Apos + (size_t)(js0 - i + KW) * PF);
    const ulonglong2* __restrict__ ap1 =
        (const ulonglong2*)(g_Apos + (size_t)(js1 - i + KW) * PF);
    const ulonglong2* __restrict__ ap2 =
        (const ulonglong2*)(g_Apos + (size_t)(js2 - i + KW) * PF);
    const ulonglong2* __restrict__ ap3 =
        (const ulonglong2*)(g_Apos + (size_t)(js3 - i + KW) * PF);
    const ulonglong2* __restrict__ sw2 = (const ulonglong2*)sW;

    // emo row into registers (packed)
    ulonglong2 er[9];
    {
        const ulonglong2* ae =
            (const ulonglong2*)(g_Aemo + (size_t)(b * L_ + i) * PF);
        #pragma unroll
        for (int t = 0; t < 9; t++) {
            int c4 = t * 32 + lane;
            if (c4 < PF / 4) er[t] = ae[c4];
            else { er[t].x = 0ull; er[t].y = 0ull; }
        }
    }
    const float bias = __ldg(b2);

    unsigned long long s0a = 0, s0b = 0, s1a = 0, s1b = 0;
    unsigned long long s2a = 0, s2b = 0, s3a = 0, s3b = 0;
    #pragma unroll
    for (int t = 0; t < 9; t++) {
        int c4 = t * 32 + lane;
        if (c4 < PF / 4) {
            ulonglong2 e = er[t];
            ulonglong2 w = sw2[c4];
            {
                ulonglong2 c = ac0[c4]; ulonglong2 q = ap0[c4];
                s0a = f2fma(f2relu(f2add(f2add(e.x, c.x), q.x)), w.x, s0a);
                s0b = f2fma(f2relu(f2add(f2add(e.y, c.y), q.y)), w.y, s0b);
            }
            {
                ulonglong2 c = ac1[c4]; ulonglong2 q = ap1[c4];
                s1a = f2fma(f2relu(f2add(f2add(e.x, c.x), q.x)), w.x, s1a);
                s1b = f2fma(f2relu(f2add(f2add(e.y, c.y), q.y)), w.y, s1b);
            }
            {
                ulonglong2 c = ac2[c4]; ulonglong2 q = ap2[c4];
                s2a = f2fma(f2relu(f2add(f2add(e.x, c.x), q.x)), w.x, s2a);
                s2b = f2fma(f2relu(f2add(f2add(e.y, c.y), q.y)), w.y, s2b);
            }
            {
                ulonglong2 c = ac3[c4]; ulonglong2 q = ap3[c4];
                s3a = f2fma(f2relu(f2add(f2add(e.x, c.x), q.x)), w.x, s3a);
                s3b = f2fma(f2relu(f2add(f2add(e.y, c.y), q.y)), w.y, s3b);
            }
        }
    }
    float s0 = f2sum(s0a) + f2sum(s0b);
    float s1 = f2sum(s1a) + f2sum(s1b);
    float s2 = f2sum(s2a) + f2sum(s2b);
    float s3 = f2sum(s3a) + f2sum(s3b);

    #pragma unroll
    for (int o = 16; o > 0; o >>= 1) {
        s0 += __shfl_xor_sync(0xFFFFFFFF, s0, o);
        s1 += __shfl_xor_sync(0xFFFFFFFF, s1, o);
        s2 += __shfl_xor_sync(0xFFFFFFFF, s2, o);
        s3 += __shfl_xor_sync(0xFFFFFFFF, s3, o);
    }
    if (lane == 0) {
        int pb = b * NPAIR + g_poff[i] + (jstart - lo);
        out[pb] = s0 + bias;
        if (cnt > 1) out[pb + 1] = s1 + bias;
        if (cnt > 2) out[pb + 2] = s2 + bias;
        if (cnt > 3) out[pb + 3] = s3 + bias;
    }
}

// ---------------- launch ------------------------------------------------------
extern "C" void kernel_launch(void* const* d_in, const int* in_sizes, int n_in,
                              void* d_out, int out_size) {
    const float* h_emo  = (const float*)d_in[0];
    const float* h_cau  = (const float*)d_in[1];
    const float* pos    = (const float*)d_in[2];
    const float* W1     = (const float*)d_in[3];
    const float* b1     = (const float*)d_in[4];
    const float* W2     = (const float*)d_in[5];
    const float* b2     = (const float*)d_in[6];
    float* out = (float*)d_out;

    const int gemm_smem = NSTAGE * STAGE_ELEMS * (int)sizeof(__nv_bfloat16);
    static bool configured = false;
    if (!configured) {
        cudaFuncSetAttribute(mma_gemm_kernel,
                             cudaFuncAttributeMaxDynamicSharedMemorySize, gemm_smem);
        configured = true;
    }

    init_pairs_kernel<<<1, 128>>>(out, out_size);
    init_f_kernel<<<(NREL * PE + 255) / 256, 256>>>(pos);
    init_apos_kernel<<<(NREL * PF + 255) / 256, 256>>>(W1, b1);
    conv_all_kernel<<<XBLK + WBLK, 256>>>(h_emo, h_cau, W1);

    dim3 ggrid(PFP / BN, M_ / BM, 2);   // (9, 16, 2)
    mma_gemm_kernel<<<ggrid, 256, gemm_smem>>>();

    int blocks = (TOTW * 32 + 255) / 256;   // 1280 blocks
    epilogue_kernel<<<blocks, 256>>>(W2, b2, out);
}

// round 14
// speedup vs baseline: 1.6249x; 1.0700x over previous
#include <cuda_runtime.h>
#include <cuda_bf16.h>
#include <math.h>
#include <stdint.h>

// Problem constants
#define B_   16
#define L_   128
#define KW   8
#define NPAIR 2104
#define GCN  512
#define PE   64
#define PF   1088
#define PFP  1152
#define M_   2048
#define NREL 17

// ---------------- scratch ----------------------------------------------------
__device__ float g_Aemo[M_ * PF];
__device__ float g_Acau[M_ * PF];
__device__ float g_Apos[NREL * PF];
__device__ float g_f[NREL * PE];
__device__ int   g_poff[L_];
__device__ __nv_bfloat16 g_Ahi[2][M_ * GCN];
__device__ __nv_bfloat16 g_Alo[2][M_ * GCN];
__device__ __nv_bfloat16 g_Bhi[2][PFP * GCN];
__device__ __nv_bfloat16 g_Blo[2][PFP * GCN];

// ---------------- init: pair offsets + emo_cau_pos tail ----------------------
__global__ void init_pairs_kernel(float* __restrict__ out, int out_size) {
    int i = threadIdx.x;
    if (i >= L_) return;
    int off = 0;
    for (int t = 0; t < i; t++) {
        int lo = t - KW; if (lo < 0) lo = 0;
        int hi = t + KW; if (hi > L_ - 1) hi = L_ - 1;
        off += hi - lo + 1;
    }
    g_poff[i] = off;
    int lo = i - KW; if (lo < 0) lo = 0;
    int hi = i + KW; if (hi > L_ - 1) hi = L_ - 1;
    if (out_size == B_ * NPAIR + 2 * NPAIR) {
        for (int j = lo; j <= hi; j++) {
            int p = off + (j - lo);
            out[B_ * NPAIR + 2 * p + 0] = (float)(i + 1);
            out[B_ * NPAIR + 2 * p + 1] = (float)(j + 1);
        }
    }
}

// ---------------- init: smoothed positional table f [17 x 64] ----------------
__global__ void init_f_kernel(const float* __restrict__ pos_emb) {
    int idx = blockIdx.x * blockDim.x + threadIdx.x;
    if (idx >= NREL * PE) return;
    int r = idx / PE;
    int e = idx % PE;
    float s = 0.f;
    #pragma unroll
    for (int d = 0; d < NREL; d++) {
        int ad = d - KW; if (ad < 0) ad = -ad;
        float cnt = (float)(L_ - ad);
        int dd = r - d;
        float w = cnt * expf(-(float)(dd * dd));
        s += w * pos_emb[d * PE + e];
    }
    g_f[idx] = s;
}

// ---------------- init: A_pos (includes b1) ----------------------------------
__global__ void init_apos_kernel(const float* __restrict__ W1,
                                 const float* __restrict__ b1) {
    int idx = blockIdx.x * blockDim.x + threadIdx.x;
    if (idx >= NREL * PF) return;
    int r = idx / PF;
    int g = idx % PF;
    float s = b1[g];
    const float* w = W1 + g * PF + 2 * GCN;
    const float* f = g_f + r * PE;
    #pragma unroll 8
    for (int e = 0; e < PE; e++) s += f[e] * w[e];
    g_Apos[idx] = s;
}

// ---------------- merged convert: X and W1 -> hi/lo bf16 ---------------------
#define XBLK (M_ * GCN / 4 / 256)        // 1024 blocks for X portion
#define WBLK (PF * GCN / 4 / 256)        // 1088 blocks for W portion

__global__ void conv_all_kernel(const float* __restrict__ Xe,
                                const float* __restrict__ Xc,
                                const float* __restrict__ W1) {
    int blk = blockIdx.x;
    if (blk < XBLK) {
        int idx = blk * 256 + threadIdx.x;
        #pragma unroll
        for (int z = 0; z < 2; z++) {
            const float* X = z ? Xc : Xe;
            float4 v = *(const float4*)(X + (size_t)idx * 4);
            __nv_bfloat16 h0 = __float2bfloat16(v.x);
            __nv_bfloat16 h1 = __float2bfloat16(v.y);
            __nv_bfloat16 h2 = __float2bfloat16(v.z);
            __nv_bfloat16 h3 = __float2bfloat16(v.w);
            __nv_bfloat162* hp = (__nv_bfloat162*)(&g_Ahi[z][(size_t)idx * 4]);
            hp[0] = __nv_bfloat162(h0, h1);
            hp[1] = __nv_bfloat162(h2, h3);
            __nv_bfloat162* lp = (__nv_bfloat162*)(&g_Alo[z][(size_t)idx * 4]);
            lp[0] = __nv_bfloat162(__float2bfloat16(v.x - __bfloat162float(h0)),
                                   __float2bfloat16(v.y - __bfloat162float(h1)));
            lp[1] = __nv_bfloat162(__float2bfloat16(v.z - __bfloat162float(h2)),
                                   __float2bfloat16(v.w - __bfloat162float(h3)));
        }
    } else {
        int idx = (blk - XBLK) * 256 + threadIdx.x;
        int g = idx / (GCN / 4), kq = idx % (GCN / 4);
        #pragma unroll
        for (int z = 0; z < 2; z++) {
            float4 v = *(const float4*)(W1 + (size_t)g * PF + z * GCN + kq * 4);
            __nv_bfloat16 h0 = __float2bfloat16(v.x);
            __nv_bfloat16 h1 = __float2bfloat16(v.y);
            __nv_bfloat16 h2 = __float2bfloat16(v.z);
            __nv_bfloat16 h3 = __float2bfloat16(v.w);
            __nv_bfloat162* hp = (__nv_bfloat162*)(&g_Bhi[z][(size_t)g * GCN + kq * 4]);
            hp[0] = __nv_bfloat162(h0, h1);
            hp[1] = __nv_bfloat162(h2, h3);
            __nv_bfloat162* lp = (__nv_bfloat162*)(&g_Blo[z][(size_t)g * GCN + kq * 4]);
            lp[0] = __nv_bfloat162(__float2bfloat16(v.x - __bfloat162float(h0)),
                                   __float2bfloat16(v.y - __bfloat162float(h1)));
            lp[1] = __nv_bfloat162(__float2bfloat16(v.z - __bfloat162float(h2)),
                                   __float2bfloat16(v.w - __bfloat162float(h3)));
        }
    }
}

// ------ bf16 tensor-core GEMM: 16 base k-tiles x 3 passes, deduped loads -----
#define BM 128
#define BN 128
#define BK 32
#define SSTR 40
#define NBASE 16
#define NSTAGE 2
#define TILE_E (BM * SSTR)              // elems per 128-row tile
#define STAGE_ELEMS (4 * TILE_E)        // Ahi, Alo, Bhi, Blo

__device__ __forceinline__ void cp16(void* smem, const void* g) {
    unsigned s = (unsigned)__cvta_generic_to_shared(smem);
    asm volatile("cp.async.cg.shared.global [%0], [%1], 16;\n" :: "r"(s), "l"(g));
}
#define CP_COMMIT() asm volatile("cp.async.commit_group;\n" ::: "memory")
#define CP_WAIT1()  asm volatile("cp.async.wait_group 1;\n" ::: "memory")
#define CP_WAIT0()  asm volatile("cp.async.wait_group 0;\n" ::: "memory")

__device__ __forceinline__ void ldsm4(unsigned& r0, unsigned& r1,
                                      unsigned& r2, unsigned& r3,
                                      const __nv_bfloat16* p) {
    unsigned a = (unsigned)__cvta_generic_to_shared(p);
    asm volatile("ldmatrix.sync.aligned.m8n8.x4.shared.b16 {%0,%1,%2,%3}, [%4];\n"
                 : "=r"(r0), "=r"(r1), "=r"(r2), "=r"(r3) : "r"(a));
}

extern __shared__ __align__(16) unsigned char dynraw[];

__global__ void __launch_bounds__(256, 2)
mma_gemm_kernel() {
    __nv_bfloat16* dynsmem = (__nv_bfloat16*)dynraw;
    const int z = blockIdx.z;
    const __nv_bfloat16* __restrict__ Ahi = g_Ahi[z];
    const __nv_bfloat16* __restrict__ Alo = g_Alo[z];
    const __nv_bfloat16* __restrict__ Bhi = g_Bhi[z];
    const __nv_bfloat16* __restrict__ Blo = g_Blo[z];
    float* __restrict__ C = z ? g_Acau : g_Aemo;

    const int tid  = threadIdx.x;
    const int lane = tid & 31;
    const int wid  = tid >> 5;
    const int wmBase = (wid & 1) * 64;
    const int wnBase = (wid >> 1) * 32;
    const int m0 = blockIdx.y * BM;
    const int n0 = blockIdx.x * BN;

    const int aRow = (lane & 7) + ((lane >> 3) & 1) * 8;
    const int aK   = (lane >> 4) * 8;
    const int bRow = (lane & 7) + (lane >> 4) * 8;
    const int bK   = ((lane >> 3) & 1) * 8;

    float acc[4][4][4];
    #pragma unroll
    for (int mt = 0; mt < 4; mt++)
        #pragma unroll
        for (int nt = 0; nt < 4; nt++)
            #pragma unroll
            for (int e = 0; e < 4; e++) acc[mt][nt][e] = 0.f;

    // load all 4 distinct tiles of base k-tile kt into stage s
    auto load_stage = [&](int kt, int s) {
        const int kc = kt * BK;
        __nv_bfloat16* sAhi = dynsmem + s * STAGE_ELEMS;
        __nv_bfloat16* sAlo = sAhi + TILE_E;
        __nv_bfloat16* sBhi = sAlo + TILE_E;
        __nv_bfloat16* sBlo = sBhi + TILE_E;
        #pragma unroll
        for (int l = 0; l < 2; l++) {
            int q = tid + l * 256;
            int row = q >> 2, c8 = (q & 3) * 8;
            size_t ga = (size_t)(m0 + row) * GCN + kc + c8;
            size_t gb = (size_t)(n0 + row) * GCN + kc + c8;
            cp16(&sAhi[row * SSTR + c8], Ahi + ga);
            cp16(&sAlo[row * SSTR + c8], Alo + ga);
            cp16(&sBhi[row * SSTR + c8], Bhi + gb);
            cp16(&sBlo[row * SSTR + c8], Blo + gb);
        }
    };

    load_stage(0, 0); CP_COMMIT();

    for (int kt = 0; kt < NBASE; kt++) {
        if (kt + 1 < NBASE) {
            load_stage(kt + 1, (kt + 1) & 1); CP_COMMIT();
            CP_WAIT1();
        } else {
            CP_WAIT0();
        }
        __syncthreads();

        const int s = kt & 1;
        const __nv_bfloat16* sAhi = dynsmem + s * STAGE_ELEMS;
        const __nv_bfloat16* sAlo = sAhi + TILE_E;
        const __nv_bfloat16* sBhi = sAlo + TILE_E;
        const __nv_bfloat16* sBlo = sBhi + TILE_E;

        #pragma unroll
        for (int pass = 0; pass < 3; pass++) {
            const __nv_bfloat16* sA = (pass == 2) ? sAlo : sAhi;
            const __nv_bfloat16* sB = (pass == 1) ? sBlo : sBhi;
            #pragma unroll
            for (int kk = 0; kk < BK; kk += 16) {
                unsigned a[4][4], b[2][4];
                #pragma unroll
                for (int mt = 0; mt < 4; mt++)
                    ldsm4(a[mt][0], a[mt][1], a[mt][2], a[mt][3],
                          &sA[(wmBase + mt * 16 + aRow) * SSTR + kk + aK]);
                #pragma unroll
                for (int ntp = 0; ntp < 2; ntp++)
                    ldsm4(b[ntp][0], b[ntp][1], b[ntp][2], b[ntp][3],
                          &sB[(wnBase + ntp * 16 + bRow) * SSTR + kk + bK]);
                #pragma unroll
                for (int mt = 0; mt < 4; mt++)
                    #pragma unroll
                    for (int nt = 0; nt < 4; nt++) {
                        unsigned b0 = b[nt >> 1][(nt & 1) * 2];
                        unsigned b1 = b[nt >> 1][(nt & 1) * 2 + 1];
                        asm volatile(
                            "mma.sync.aligned.m16n8k16.row.col.f32.bf16.bf16.f32 "
                            "{%0,%1,%2,%3}, {%4,%5,%6,%7}, {%8,%9}, {%0,%1,%2,%3};\n"
                            : "+f"(acc[mt][nt][0]), "+f"(acc[mt][nt][1]),
                              "+f"(acc[mt][nt][2]), "+f"(acc[mt][nt][3])
                            : "r"(a[mt][0]), "r"(a[mt][1]), "r"(a[mt][2]), "r"(a[mt][3]),
                              "r"(b0), "r"(b1));
                    }
            }
        }
        __syncthreads();
    }

    #pragma unroll
    for (int mt = 0; mt < 4; mt++) {
        int row = m0 + wmBase + mt * 16 + (lane >> 2);
        #pragma unroll
        for (int nt = 0; nt < 4; nt++) {
            int col = n0 + wnBase + nt * 8 + (lane & 3) * 2;
            if (col < PF) {
                *(float2*)&C[(size_t)row * PF + col] =
                    make_float2(acc[mt][nt][0], acc[mt][nt][1]);
                *(float2*)&C[(size_t)(row + 8) * PF + col] =
                    make_float2(acc[mt][nt][2], acc[mt][nt][3]);
            }
        }
    }
}

// ---------------- packed f32x2 helpers ---------------------------------------
__device__ __forceinline__ unsigned long long f2add(unsigned long long a,
                                                    unsigned long long b) {
    unsigned long long r;
    asm("add.rn.f32x2 %0, %1, %2;" : "=l"(r) : "l"(a), "l"(b));
    return r;
}
__device__ __forceinline__ unsigned long long f2fma(unsigned long long a,
                                                    unsigned long long b,
                                                    unsigned long long c) {
    unsigned long long r;
    asm("fma.rn.f32x2 %0, %1, %2, %3;" : "=l"(r) : "l"(a), "l"(b), "l"(c));
    return r;
}
__device__ __forceinline__ unsigned long long f2relu(unsigned long long v) {
    float lo, hi;
    asm("mov.b64 {%0,%1}, %2;" : "=f"(lo), "=f"(hi) : "l"(v));
    lo = fmaxf(lo, 0.f);
    hi = fmaxf(hi, 0.f);
    unsigned long long r;
    asm("mov.b64 %0, {%1,%2};" : "=l"(r) : "f"(lo), "f"(hi));
    return r;
}
__device__ __forceinline__ float f2sum(unsigned long long v) {
    float lo, hi;
    asm("mov.b64 {%0,%1}, %2;" : "=f"(lo), "=f"(hi) : "l"(v));
    return lo + hi;
}

// ---------------- epilogue: warp/(b,i,4j), packed f32x2, W2 in smem ----------
#define WPI 5
#define TOTW (B_ * L_ * WPI)

__global__ void __launch_bounds__(256)
epilogue_kernel(const float* __restrict__ W2, const float* __restrict__ b2,
                float* __restrict__ out) {
    __shared__ __align__(16) float sW[PF];

    const int tid  = threadIdx.x;
    const int lane = tid & 31;
    const int wid  = tid >> 5;

    {
        const float4* src = (const float4*)W2;
        float4* dst = (float4*)sW;
        for (int q = tid; q < PF / 4; q += 256) dst[q] = src[q];
    }
    __syncthreads();

    int gw = blockIdx.x * 8 + wid;
    if (gw >= TOTW) return;
    int b   = gw / (L_ * WPI);
    int rem = gw - b * (L_ * WPI);
    int i   = rem / WPI;
    int k   = rem - i * WPI;

    int lo = i - KW; if (lo < 0) lo = 0;
    int hi = i + KW; if (hi > L_ - 1) hi = L_ - 1;
    int jstart = lo + 4 * k;
    if (jstart > hi) return;
    int cnt = hi - jstart + 1; if (cnt > 4) cnt = 4;

    int js0 = jstart;
    int js1 = jstart + 1 > hi ? hi : jstart + 1;
    int js2 = jstart + 2 > hi ? hi : jstart + 2;
    int js3 = jstart + 3 > hi ? hi : jstart + 3;

    const ulonglong2* __restrict__ ac0 =
        (const ulonglong2*)(g_Acau + (size_t)(b * L_ + js0) * PF);
    const ulonglong2* __restrict__ ac1 =
        (const ulonglong2*)(g_Acau + (size_t)(b * L_ + js1) * PF);
    const ulonglong2* __restrict__ ac2 =
        (const ulonglong2*)(g_Acau + (size_t)(b * L_ + js2) * PF);
    const ulonglong2* __restrict__ ac3 =
        (const ulonglong2*)(g_Acau + (size_t)(b * L_ + js3) * PF);
    const ulonglong2* __restrict__ ap0 =
        (const ulonglong2*)(g_Apos + (size_t)(js0 - i + KW) * PF);
    const ulonglong2* __restrict__ ap1 =
        (const ulonglong2*)(g_Apos + (size_t)(js1 - i + KW) * PF);
    const ulonglong2* __restrict__ ap2 =
        (const ulonglong2*)(g_Apos + (size_t)(js2 - i + KW) * PF);
    const ulonglong2* __restrict__ ap3 =
        (const ulonglong2*)(g_Apos + (size_t)(js3 - i + KW) * PF);
    const ulonglong2* __restrict__ sw2 = (const ulonglong2*)sW;

    // emo row into registers (packed)
    ulonglong2 er[9];
    {
        const ulonglong2* ae =
            (const ulonglong2*)(g_Aemo + (size_t)(b * L_ + i) * PF);
        #pragma unroll
        for (int t = 0; t < 9; t++) {
            int c4 = t * 32 + lane;
            if (c4 < PF / 4) er[t] = ae[c4];
            else { er[t].x = 0ull; er[t].y = 0ull; }
        }
    }
    const float bias = __ldg(b2);

    unsigned long long s0a = 0, s0b = 0, s1a = 0, s1b = 0;
    unsigned long long s2a = 0, s2b = 0, s3a = 0, s3b = 0;
    #pragma unroll
    for (int t = 0; t < 9; t++) {
        int c4 = t * 32 + lane;
        if (c4 < PF / 4) {
            ulonglong2 e = er[t];
            ulonglong2 w = sw2[c4];
            {
                ulonglong2 c = ac0[c4]; ulonglong2 q = ap0[c4];
                s0a = f2fma(f2relu(f2add(f2add(e.x, c.x), q.x)), w.x, s0a);
                s0b = f2fma(f2relu(f2add(f2add(e.y, c.y), q.y)), w.y, s0b);
            }
            {
                ulonglong2 c = ac1[c4]; ulonglong2 q = ap1[c4];
                s1a = f2fma(f2relu(f2add(f2add(e.x, c.x), q.x)), w.x, s1a);
                s1b = f2fma(f2relu(f2add(f2add(e.y, c.y), q.y)), w.y, s1b);
            }
            {
                ulonglong2 c = ac2[c4]; ulonglong2 q = ap2[c4];
                s2a = f2fma(f2relu(f2add(f2add(e.x, c.x), q.x)), w.x, s2a);
                s2b = f2fma(f2relu(f2add(f2add(e.y, c.y), q.y)), w.y, s2b);
            }
            {
                ulonglong2 c = ac3[c4]; ulonglong2 q = ap3[c4];
                s3a = f2fma(f2relu(f2add(f2add(e.x, c.x), q.x)), w.x, s3a);
                s3b = f2fma(f2relu(f2add(f2add(e.y, c.y), q.y)), w.y, s3b);
            }
        }
    }
    float s0 = f2sum(s0a) + f2sum(s0b);
    float s1 = f2sum(s1a) + f2sum(s1b);
    float s2 = f2sum(s2a) + f2sum(s2b);
    float s3 = f2sum(s3a) + f2sum(s3b);

    #pragma unroll
    for (int o = 16; o > 0; o >>= 1) {
        s0 += __shfl_xor_sync(0xFFFFFFFF, s0, o);
        s1 += __shfl_xor_sync(0xFFFFFFFF, s1, o);
        s2 += __shfl_xor_sync(0xFFFFFFFF, s2, o);
        s3 += __shfl_xor_sync(0xFFFFFFFF, s3, o);
    }
    if (lane == 0) {
        int pb = b * NPAIR + g_poff[i] + (jstart - lo);
        out[pb] = s0 + bias;
        if (cnt > 1) out[pb + 1] = s1 + bias;
        if (cnt > 2) out[pb + 2] = s2 + bias;
        if (cnt > 3) out[pb + 3] = s3 + bias;
    }
}

// ---------------- launch ------------------------------------------------------
extern "C" void kernel_launch(void* const* d_in, const int* in_sizes, int n_in,
                              void* d_out, int out_size) {
    const float* h_emo  = (const float*)d_in[0];
    const float* h_cau  = (const float*)d_in[1];
    const float* pos    = (const float*)d_in[2];
    const float* W1     = (const float*)d_in[3];
    const float* b1     = (const float*)d_in[4];
    const float* W2     = (const float*)d_in[5];
    const float* b2     = (const float*)d_in[6];
    float* out = (float*)d_out;

    const int gemm_smem = NSTAGE * STAGE_ELEMS * (int)sizeof(__nv_bfloat16);
    static bool configured = false;
    if (!configured) {
        cudaFuncSetAttribute(mma_gemm_kernel,
                             cudaFuncAttributeMaxDynamicSharedMemorySize, gemm_smem);
        configured = true;
    }

    init_pairs_kernel<<<1, 128>>>(out, out_size);
    init_f_kernel<<<(NREL * PE + 255) / 256, 256>>>(pos);
    init_apos_kernel<<<(NREL * PF + 255) / 256, 256>>>(W1, b1);
    conv_all_kernel<<<XBLK + WBLK, 256>>>(h_emo, h_cau, W1);

    dim3 ggrid(PFP / BN, M_ / BM, 2);   // (9, 16, 2)
    mma_gemm_kernel<<<ggrid, 256, gemm_smem>>>();

    int blocks = (TOTW * 32 + 255) / 256;   // 1280 blocks
    epilogue_kernel<<<blocks, 256>>>(W2, b2, out);
}

// round 15
// speedup vs baseline: 1.9603x; 1.2065x over previous
#include <cuda_runtime.h>
#include <cuda_bf16.h>
#include <cuda_fp16.h>
#include <math.h>
#include <stdint.h>

// Problem constants
#define B_   16
#define L_   128
#define KW   8
#define NPAIR 2104
#define GCN  512
#define PE   64
#define PF   1088
#define PFP  1152
#define M_   2048
#define NREL 17

// ---------------- scratch ----------------------------------------------------
__device__ float g_Aemo[M_ * PF];
__device__ float g_Acau[M_ * PF];
__device__ float g_Apos[NREL * PF];
__device__ float g_f[NREL * PE];
__device__ int   g_poff[L_];
__device__ __half g_Ah[2][M_ * GCN];       // A single fp16
__device__ __half g_Bhi[2][PFP * GCN];     // B hi fp16
__device__ __half g_Blo[2][PFP * GCN];     // B lo fp16

// ---------------- init: pair offsets + emo_cau_pos tail ----------------------
__global__ void init_pairs_kernel(float* __restrict__ out, int out_size) {
    int i = threadIdx.x;
    if (i >= L_) return;
    int off = 0;
    for (int t = 0; t < i; t++) {
        int lo = t - KW; if (lo < 0) lo = 0;
        int hi = t + KW; if (hi > L_ - 1) hi = L_ - 1;
        off += hi - lo + 1;
    }
    g_poff[i] = off;
    int lo = i - KW; if (lo < 0) lo = 0;
    int hi = i + KW; if (hi > L_ - 1) hi = L_ - 1;
    if (out_size == B_ * NPAIR + 2 * NPAIR) {
        for (int j = lo; j <= hi; j++) {
            int p = off + (j - lo);
            out[B_ * NPAIR + 2 * p + 0] = (float)(i + 1);
            out[B_ * NPAIR + 2 * p + 1] = (float)(j + 1);
        }
    }
}

// ---------------- init: smoothed positional table f [17 x 64] ----------------
__global__ void init_f_kernel(const float* __restrict__ pos_emb) {
    int idx = blockIdx.x * blockDim.x + threadIdx.x;
    if (idx >= NREL * PE) return;
    int r = idx / PE;
    int e = idx % PE;
    float s = 0.f;
    #pragma unroll
    for (int d = 0; d < NREL; d++) {
        int ad = d - KW; if (ad < 0) ad = -ad;
        float cnt = (float)(L_ - ad);
        int dd = r - d;
        float w = cnt * expf(-(float)(dd * dd));
        s += w * pos_emb[d * PE + e];
    }
    g_f[idx] = s;
}

// ---------------- init: A_pos (includes b1) ----------------------------------
__global__ void init_apos_kernel(const float* __restrict__ W1,
                                 const float* __restrict__ b1) {
    int idx = blockIdx.x * blockDim.x + threadIdx.x;
    if (idx >= NREL * PF) return;
    int r = idx / PF;
    int g = idx % PF;
    float s = b1[g];
    const float* w = W1 + g * PF + 2 * GCN;
    const float* f = g_f + r * PE;
    #pragma unroll 8
    for (int e = 0; e < PE; e++) s += f[e] * w[e];
    g_Apos[idx] = s;
}

// ---------------- merged convert: X (fp16) and W1 (fp16 hi/lo) ---------------
#define XBLK (M_ * GCN / 4 / 256)        // 1024 blocks for X portion
#define WBLK (PF * GCN / 4 / 256)        // 1088 blocks for W portion

__global__ void conv_all_kernel(const float* __restrict__ Xe,
                                const float* __restrict__ Xc,
                                const float* __restrict__ W1) {
    int blk = blockIdx.x;
    if (blk < XBLK) {
        int idx = blk * 256 + threadIdx.x;
        #pragma unroll
        for (int z = 0; z < 2; z++) {
            const float* X = z ? Xc : Xe;
            float4 v = *(const float4*)(X + (size_t)idx * 4);
            __half2* hp = (__half2*)(&g_Ah[z][(size_t)idx * 4]);
            hp[0] = __floats2half2_rn(v.x, v.y);
            hp[1] = __floats2half2_rn(v.z, v.w);
        }
    } else {
        int idx = (blk - XBLK) * 256 + threadIdx.x;
        int g = idx / (GCN / 4), kq = idx % (GCN / 4);
        #pragma unroll
        for (int z = 0; z < 2; z++) {
            float4 v = *(const float4*)(W1 + (size_t)g * PF + z * GCN + kq * 4);
            __half h0 = __float2half_rn(v.x);
            __half h1 = __float2half_rn(v.y);
            __half h2 = __float2half_rn(v.z);
            __half h3 = __float2half_rn(v.w);
            __half2* hp = (__half2*)(&g_Bhi[z][(size_t)g * GCN + kq * 4]);
            hp[0] = __half2(h0, h1);
            hp[1] = __half2(h2, h3);
            __half2* lp = (__half2*)(&g_Blo[z][(size_t)g * GCN + kq * 4]);
            lp[0] = __half2(__float2half_rn(v.x - __half2float(h0)),
                            __float2half_rn(v.y - __half2float(h1)));
            lp[1] = __half2(__float2half_rn(v.z - __half2float(h2)),
                            __float2half_rn(v.w - __half2float(h3)));
        }
    }
}

// ------ fp16 tensor-core GEMM: 16 base k-tiles x 2 passes (A, Bhi, Blo) ------
#define BM 128
#define BN 128
#define BK 32
#define SSTR 40
#define NBASE 16
#define NSTAGE 2
#define TILE_E (BM * SSTR)              // elems per 128-row tile
#define STAGE_ELEMS (3 * TILE_E)        // A, Bhi, Blo

__device__ __forceinline__ void cp16(void* smem, const void* g) {
    unsigned s = (unsigned)__cvta_generic_to_shared(smem);
    asm volatile("cp.async.cg.shared.global [%0], [%1], 16;\n" :: "r"(s), "l"(g));
}
#define CP_COMMIT() asm volatile("cp.async.commit_group;\n" ::: "memory")
#define CP_WAIT1()  asm volatile("cp.async.wait_group 1;\n" ::: "memory")
#define CP_WAIT0()  asm volatile("cp.async.wait_group 0;\n" ::: "memory")

__device__ __forceinline__ void ldsm4(unsigned& r0, unsigned& r1,
                                      unsigned& r2, unsigned& r3,
                                      const __half* p) {
    unsigned a = (unsigned)__cvta_generic_to_shared(p);
    asm volatile("ldmatrix.sync.aligned.m8n8.x4.shared.b16 {%0,%1,%2,%3}, [%4];\n"
                 : "=r"(r0), "=r"(r1), "=r"(r2), "=r"(r3) : "r"(a));
}

extern __shared__ __align__(16) unsigned char dynraw[];

__global__ void __launch_bounds__(256, 2)
mma_gemm_kernel() {
    __half* dynsmem = (__half*)dynraw;
    const int z = blockIdx.z;
    const __half* __restrict__ Ah  = g_Ah[z];
    const __half* __restrict__ Bhi = g_Bhi[z];
    const __half* __restrict__ Blo = g_Blo[z];
    float* __restrict__ C = z ? g_Acau : g_Aemo;

    const int tid  = threadIdx.x;
    const int lane = tid & 31;
    const int wid  = tid >> 5;
    const int wmBase = (wid & 1) * 64;
    const int wnBase = (wid >> 1) * 32;
    const int m0 = blockIdx.y * BM;
    const int n0 = blockIdx.x * BN;

    const int aRow = (lane & 7) + ((lane >> 3) & 1) * 8;
    const int aK   = (lane >> 4) * 8;
    const int bRow = (lane & 7) + (lane >> 4) * 8;
    const int bK   = ((lane >> 3) & 1) * 8;

    float acc[4][4][4];
    #pragma unroll
    for (int mt = 0; mt < 4; mt++)
        #pragma unroll
        for (int nt = 0; nt < 4; nt++)
            #pragma unroll
            for (int e = 0; e < 4; e++) acc[mt][nt][e] = 0.f;

    // load the 3 distinct tiles of base k-tile kt into stage s
    auto load_stage = [&](int kt, int s) {
        const int kc = kt * BK;
        __half* sA   = dynsmem + s * STAGE_ELEMS;
        __half* sBhi = sA + TILE_E;
        __half* sBlo = sBhi + TILE_E;
        #pragma unroll
        for (int l = 0; l < 2; l++) {
            int q = tid + l * 256;
            int row = q >> 2, c8 = (q & 3) * 8;
            size_t ga = (size_t)(m0 + row) * GCN + kc + c8;
            size_t gb = (size_t)(n0 + row) * GCN + kc + c8;
            cp16(&sA[row * SSTR + c8],   Ah  + ga);
            cp16(&sBhi[row * SSTR + c8], Bhi + gb);
            cp16(&sBlo[row * SSTR + c8], Blo + gb);
        }
    };

    load_stage(0, 0); CP_COMMIT();

    for (int kt = 0; kt < NBASE; kt++) {
        if (kt + 1 < NBASE) {
            load_stage(kt + 1, (kt + 1) & 1); CP_COMMIT();
            CP_WAIT1();
        } else {
            CP_WAIT0();
        }
        __syncthreads();

        const int s = kt & 1;
        const __half* sA   = dynsmem + s * STAGE_ELEMS;
        const __half* sBhi = sA + TILE_E;
        const __half* sBlo = sBhi + TILE_E;

        #pragma unroll
        for (int pass = 0; pass < 2; pass++) {
            const __half* sB = pass ? sBlo : sBhi;
            #pragma unroll
            for (int kk = 0; kk < BK; kk += 16) {
                unsigned a[4][4], b[2][4];
                #pragma unroll
                for (int mt = 0; mt < 4; mt++)
                    ldsm4(a[mt][0], a[mt][1], a[mt][2], a[mt][3],
                          &sA[(wmBase + mt * 16 + aRow) * SSTR + kk + aK]);
                #pragma unroll
                for (int ntp = 0; ntp < 2; ntp++)
                    ldsm4(b[ntp][0], b[ntp][1], b[ntp][2], b[ntp][3],
                          &sB[(wnBase + ntp * 16 + bRow) * SSTR + kk + bK]);
                #pragma unroll
                for (int mt = 0; mt < 4; mt++)
                    #pragma unroll
                    for (int nt = 0; nt < 4; nt++) {
                        unsigned b0 = b[nt >> 1][(nt & 1) * 2];
                        unsigned b1 = b[nt >> 1][(nt & 1) * 2 + 1];
                        asm volatile(
                            "mma.sync.aligned.m16n8k16.row.col.f32.f16.f16.f32 "
                            "{%0,%1,%2,%3}, {%4,%5,%6,%7}, {%8,%9}, {%0,%1,%2,%3};\n"
                            : "+f"(acc[mt][nt][0]), "+f"(acc[mt][nt][1]),
                              "+f"(acc[mt][nt][2]), "+f"(acc[mt][nt][3])
                            : "r"(a[mt][0]), "r"(a[mt][1]), "r"(a[mt][2]), "r"(a[mt][3]),
                              "r"(b0), "r"(b1));
                    }
            }
        }
        __syncthreads();
    }

    #pragma unroll
    for (int mt = 0; mt < 4; mt++) {
        int row = m0 + wmBase + mt * 16 + (lane >> 2);
        #pragma unroll
        for (int nt = 0; nt < 4; nt++) {
            int col = n0 + wnBase + nt * 8 + (lane & 3) * 2;
            if (col < PF) {
                *(float2*)&C[(size_t)row * PF + col] =
                    make_float2(acc[mt][nt][0], acc[mt][nt][1]);
                *(float2*)&C[(size_t)(row + 8) * PF + col] =
                    make_float2(acc[mt][nt][2], acc[mt][nt][3]);
            }
        }
    }
}

// ---------------- packed f32x2 helpers ---------------------------------------
__device__ __forceinline__ unsigned long long f2add(unsigned long long a,
                                                    unsigned long long b) {
    unsigned long long r;
    asm("add.rn.f32x2 %0, %1, %2;" : "=l"(r) : "l"(a), "l"(b));
    return r;
}
__device__ __forceinline__ unsigned long long f2fma(unsigned long long a,
                                                    unsigned long long b,
                                                    unsigned long long c) {
    unsigned long long r;
    asm("fma.rn.f32x2 %0, %1, %2, %3;" : "=l"(r) : "l"(a), "l"(b), "l"(c));
    return r;
}
__device__ __forceinline__ unsigned long long f2relu(unsigned long long v) {
    float lo, hi;
    asm("mov.b64 {%0,%1}, %2;" : "=f"(lo), "=f"(hi) : "l"(v));
    lo = fmaxf(lo, 0.f);
    hi = fmaxf(hi, 0.f);
    unsigned long long r;
    asm("mov.b64 %0, {%1,%2};" : "=l"(r) : "f"(lo), "f"(hi));
    return r;
}
__device__ __forceinline__ float f2sum(unsigned long long v) {
    float lo, hi;
    asm("mov.b64 {%0,%1}, %2;" : "=f"(lo), "=f"(hi) : "l"(v));
    return lo + hi;
}

// ---------------- epilogue: warp/(b,i,4j), packed f32x2, W2 in smem ----------
#define WPI 5
#define TOTW (B_ * L_ * WPI)

__global__ void __launch_bounds__(256)
epilogue_kernel(const float* __restrict__ W2, const float* __restrict__ b2,
                float* __restrict__ out) {
    __shared__ __align__(16) float sW[PF];

    const int tid  = threadIdx.x;
    const int lane = tid & 31;
    const int wid  = tid >> 5;

    {
        const float4* src = (const float4*)W2;
        float4* dst = (float4*)sW;
        for (int q = tid; q < PF / 4; q += 256) dst[q] = src[q];
    }
    __syncthreads();

    int gw = blockIdx.x * 8 + wid;
    if (gw >= TOTW) return;
    int b   = gw / (L_ * WPI);
    int rem = gw - b * (L_ * WPI);
    int i   = rem / WPI;
    int k   = rem - i * WPI;

    int lo = i - KW; if (lo < 0) lo = 0;
    int hi = i + KW; if (hi > L_ - 1) hi = L_ - 1;
    int jstart = lo + 4 * k;
    if (jstart > hi) return;
    int cnt = hi - jstart + 1; if (cnt > 4) cnt = 4;

    int js0 = jstart;
    int js1 = jstart + 1 > hi ? hi : jstart + 1;
    int js2 = jstart + 2 > hi ? hi : jstart + 2;
    int js3 = jstart + 3 > hi ? hi : jstart + 3;

    const ulonglong2* __restrict__ ac0 =
        (const ulonglong2*)(g_Acau + (size_t)(b * L_ + js0) * PF);
    const ulonglong2* __restrict__ ac1 =
        (const ulonglong2*)(g_Acau + (size_t)(b * L_ + js1) * PF);
    const ulonglong2* __restrict__ ac2 =
        (const ulonglong2*)(g_Acau + (size_t)(b * L_ + js2) * PF);
    const ulonglong2* __restrict__ ac3 =
        (const ulonglong2*)(g_Acau + (size_t)(b * L_ + js3) * PF);
    const ulonglong2* __restrict__ ap0 =
        (const ulonglong2*)(g_Apos + (size_t)(js0 - i + KW) * PF);
    const ulonglong2* __restrict__ ap1 =
        (const ulonglong2*)(g_Apos + (size_t)(js1 - i + KW) * PF);
    const ulonglong2* __restrict__ ap2 =
        (const ulonglong2*)(g_Apos + (size_t)(js2 - i + KW) * PF);
    const ulonglong2* __restrict__ ap3 =
        (const ulonglong2*)(g_Apos + (size_t)(js3 - i + KW) * PF);
    const ulonglong2* __restrict__ sw2 = (const ulonglong2*)sW;

    // emo row into registers (packed)
    ulonglong2 er[9];
    {
        const ulonglong2* ae =
            (const ulonglong2*)(g_Aemo + (size_t)(b * L_ + i) * PF);
        #pragma unroll
        for (int t = 0; t < 9; t++) {
            int c4 = t * 32 + lane;
            if (c4 < PF / 4) er[t] = ae[c4];
            else { er[t].x = 0ull; er[t].y = 0ull; }
        }
    }
    const float bias = __ldg(b2);

    unsigned long long s0a = 0, s0b = 0, s1a = 0, s1b = 0;
    unsigned long long s2a = 0, s2b = 0, s3a = 0, s3b = 0;
    #pragma unroll
    for (int t = 0; t < 9; t++) {
        int c4 = t * 32 + lane;
        if (c4 < PF / 4) {
            ulonglong2 e = er[t];
            ulonglong2 w = sw2[c4];
            {
                ulonglong2 c = ac0[c4]; ulonglong2 q = ap0[c4];
                s0a = f2fma(f2relu(f2add(f2add(e.x, c.x), q.x)), w.x, s0a);
                s0b = f2fma(f2relu(f2add(f2add(e.y, c.y), q.y)), w.y, s0b);
            }
            {
                ulonglong2 c = ac1[c4]; ulonglong2 q = ap1[c4];
                s1a = f2fma(f2relu(f2add(f2add(e.x, c.x), q.x)), w.x, s1a);
                s1b = f2fma(f2relu(f2add(f2add(e.y, c.y), q.y)), w.y, s1b);
            }
            {
                ulonglong2 c = ac2[c4]; ulonglong2 q = ap2[c4];
                s2a = f2fma(f2relu(f2add(f2add(e.x, c.x), q.x)), w.x, s2a);
                s2b = f2fma(f2relu(f2add(f2add(e.y, c.y), q.y)), w.y, s2b);
            }
            {
                ulonglong2 c = ac3[c4]; ulonglong2 q = ap3[c4];
                s3a = f2fma(f2relu(f2add(f2add(e.x, c.x), q.x)), w.x, s3a);
                s3b = f2fma(f2relu(f2add(f2add(e.y, c.y), q.y)), w.y, s3b);
            }
        }
    }
    float s0 = f2sum(s0a) + f2sum(s0b);
    float s1 = f2sum(s1a) + f2sum(s1b);
    float s2 = f2sum(s2a) + f2sum(s2b);
    float s3 = f2sum(s3a) + f2sum(s3b);

    #pragma unroll
    for (int o = 16; o > 0; o >>= 1) {
        s0 += __shfl_xor_sync(0xFFFFFFFF, s0, o);
        s1 += __shfl_xor_sync(0xFFFFFFFF, s1, o);
        s2 += __shfl_xor_sync(0xFFFFFFFF, s2, o);
        s3 += __shfl_xor_sync(0xFFFFFFFF, s3, o);
    }
    if (lane == 0) {
        int pb = b * NPAIR + g_poff[i] + (jstart - lo);
        out[pb] = s0 + bias;
        if (cnt > 1) out[pb + 1] = s1 + bias;
        if (cnt > 2) out[pb + 2] = s2 + bias;
        if (cnt > 3) out[pb + 3] = s3 + bias;
    }
}

// ---------------- launch ------------------------------------------------------
extern "C" void kernel_launch(void* const* d_in, const int* in_sizes, int n_in,
                              void* d_out, int out_size) {
    const float* h_emo  = (const float*)d_in[0];
    const float* h_cau  = (const float*)d_in[1];
    const float* pos    = (const float*)d_in[2];
    const float* W1     = (const float*)d_in[3];
    const float* b1     = (const float*)d_in[4];
    const float* W2     = (const float*)d_in[5];
    const float* b2     = (const float*)d_in[6];
    float* out = (float*)d_out;

    const int gemm_smem = NSTAGE * STAGE_ELEMS * (int)sizeof(__half);
    static bool configured = false;
    if (!configured) {
        cudaFuncSetAttribute(mma_gemm_kernel,
                             cudaFuncAttributeMaxDynamicSharedMemorySize, gemm_smem);
        configured = true;
    }

    init_pairs_kernel<<<1, 128>>>(out, out_size);
    init_f_kernel<<<(NREL * PE + 255) / 256, 256>>>(pos);
    init_apos_kernel<<<(NREL * PF + 255) / 256, 256>>>(W1, b1);
    conv_all_kernel<<<XBLK + WBLK, 256>>>(h_emo, h_cau, W1);

    dim3 ggrid(PFP / BN, M_ / BM, 2);   // (9, 16, 2)
    mma_gemm_kernel<<<ggrid, 256, gemm_smem>>>();

    int blocks = (TOTW * 32 + 255) / 256;   // 1280 blocks
    epilogue_kernel<<<blocks, 256>>>(W2, b2, out);
}

// round 16
// speedup vs baseline: 2.4425x; 1.2460x over previous
#include <cuda_runtime.h>
#include <cuda_bf16.h>
#include <cuda_fp16.h>
#include <math.h>
#include <stdint.h>

// Problem constants
#define B_   16
#define L_   128
#define KW   8
#define NPAIR 2104
#define GCN  512
#define PE   64
#define PF   1088
#define PFP  1152
#define M_   2048
#define NREL 17

// ---------------- scratch ----------------------------------------------------
__device__ float g_Aemo[M_ * PF];
__device__ float g_Acau[M_ * PF];
__device__ float g_Apos[NREL * PF];
__device__ float g_f[NREL * PE];
__device__ int   g_poff[L_];
__device__ __half g_Ah[2][M_ * GCN];       // A fp16
__device__ __half g_Bh[2][PFP * GCN];      // B fp16

// ---------------- init: pair offsets + emo_cau_pos tail ----------------------
__global__ void init_pairs_kernel(float* __restrict__ out, int out_size) {
    int i = threadIdx.x;
    if (i >= L_) return;
    int off = 0;
    for (int t = 0; t < i; t++) {
        int lo = t - KW; if (lo < 0) lo = 0;
        int hi = t + KW; if (hi > L_ - 1) hi = L_ - 1;
        off += hi - lo + 1;
    }
    g_poff[i] = off;
    int lo = i - KW; if (lo < 0) lo = 0;
    int hi = i + KW; if (hi > L_ - 1) hi = L_ - 1;
    if (out_size == B_ * NPAIR + 2 * NPAIR) {
        for (int j = lo; j <= hi; j++) {
            int p = off + (j - lo);
            out[B_ * NPAIR + 2 * p + 0] = (float)(i + 1);
            out[B_ * NPAIR + 2 * p + 1] = (float)(j + 1);
        }
    }
}

// ---------------- init: smoothed positional table f [17 x 64] ----------------
__global__ void init_f_kernel(const float* __restrict__ pos_emb) {
    int idx = blockIdx.x * blockDim.x + threadIdx.x;
    if (idx >= NREL * PE) return;
    int r = idx / PE;
    int e = idx % PE;
    float s = 0.f;
    #pragma unroll
    for (int d = 0; d < NREL; d++) {
        int ad = d - KW; if (ad < 0) ad = -ad;
        float cnt = (float)(L_ - ad);
        int dd = r - d;
        float w = cnt * expf(-(float)(dd * dd));
        s += w * pos_emb[d * PE + e];
    }
    g_f[idx] = s;
}

// ---------------- init: A_pos (includes b1) ----------------------------------
__global__ void init_apos_kernel(const float* __restrict__ W1,
                                 const float* __restrict__ b1) {
    int idx = blockIdx.x * blockDim.x + threadIdx.x;
    if (idx >= NREL * PF) return;
    int r = idx / PF;
    int g = idx % PF;
    float s = b1[g];
    const float* w = W1 + g * PF + 2 * GCN;
    const float* f = g_f + r * PE;
    #pragma unroll 8
    for (int e = 0; e < PE; e++) s += f[e] * w[e];
    g_Apos[idx] = s;
}

// ---------------- merged convert: X and W1 -> fp16 ---------------------------
#define XBLK (M_ * GCN / 4 / 256)        // 1024 blocks for X portion
#define WBLK (PF * GCN / 4 / 256)        // 1088 blocks for W portion

__global__ void conv_all_kernel(const float* __restrict__ Xe,
                                const float* __restrict__ Xc,
                                const float* __restrict__ W1) {
    int blk = blockIdx.x;
    if (blk < XBLK) {
        int idx = blk * 256 + threadIdx.x;
        #pragma unroll
        for (int z = 0; z < 2; z++) {
            const float* X = z ? Xc : Xe;
            float4 v = *(const float4*)(X + (size_t)idx * 4);
            __half2* hp = (__half2*)(&g_Ah[z][(size_t)idx * 4]);
            hp[0] = __floats2half2_rn(v.x, v.y);
            hp[1] = __floats2half2_rn(v.z, v.w);
        }
    } else {
        int idx = (blk - XBLK) * 256 + threadIdx.x;
        int g = idx / (GCN / 4), kq = idx % (GCN / 4);
        #pragma unroll
        for (int z = 0; z < 2; z++) {
            float4 v = *(const float4*)(W1 + (size_t)g * PF + z * GCN + kq * 4);
            __half2* hp = (__half2*)(&g_Bh[z][(size_t)g * GCN + kq * 4]);
            hp[0] = __floats2half2_rn(v.x, v.y);
            hp[1] = __floats2half2_rn(v.z, v.w);
        }
    }
}

// ------ fp16 tensor-core GEMM: 128x128x32, single pass, 3-stage --------------
#define BM 128
#define BN 128
#define BK 32
#define SSTR 40
#define NBASE 16
#define NSTAGE 3
#define TILE_E (BM * SSTR)
#define STAGE_ELEMS (2 * TILE_E)        // A, B

__device__ __forceinline__ void cp16(void* smem, const void* g) {
    unsigned s = (unsigned)__cvta_generic_to_shared(smem);
    asm volatile("cp.async.cg.shared.global [%0], [%1], 16;\n" :: "r"(s), "l"(g));
}
#define CP_COMMIT() asm volatile("cp.async.commit_group;\n" ::: "memory")
#define CP_WAIT1()  asm volatile("cp.async.wait_group 1;\n" ::: "memory")

__device__ __forceinline__ void ldsm4(unsigned& r0, unsigned& r1,
                                      unsigned& r2, unsigned& r3,
                                      const __half* p) {
    unsigned a = (unsigned)__cvta_generic_to_shared(p);
    asm volatile("ldmatrix.sync.aligned.m8n8.x4.shared.b16 {%0,%1,%2,%3}, [%4];\n"
                 : "=r"(r0), "=r"(r1), "=r"(r2), "=r"(r3) : "r"(a));
}

extern __shared__ __align__(16) unsigned char dynraw[];

__global__ void __launch_bounds__(256, 2)
mma_gemm_kernel() {
    __half* dynsmem = (__half*)dynraw;
    const int z = blockIdx.z;
    const __half* __restrict__ Ah = g_Ah[z];
    const __half* __restrict__ Bh = g_Bh[z];
    float* __restrict__ C = z ? g_Acau : g_Aemo;

    const int tid  = threadIdx.x;
    const int lane = tid & 31;
    const int wid  = tid >> 5;
    const int wmBase = (wid & 1) * 64;
    const int wnBase = (wid >> 1) * 32;
    const int m0 = blockIdx.y * BM;
    const int n0 = blockIdx.x * BN;

    const int aRow = (lane & 7) + ((lane >> 3) & 1) * 8;
    const int aK   = (lane >> 4) * 8;
    const int bRow = (lane & 7) + (lane >> 4) * 8;
    const int bK   = ((lane >> 3) & 1) * 8;

    float acc[4][4][4];
    #pragma unroll
    for (int mt = 0; mt < 4; mt++)
        #pragma unroll
        for (int nt = 0; nt < 4; nt++)
            #pragma unroll
            for (int e = 0; e < 4; e++) acc[mt][nt][e] = 0.f;

    auto load_stage = [&](int kt, int s) {
        const int kc = kt * BK;
        __half* sA = dynsmem + s * STAGE_ELEMS;
        __half* sB = sA + TILE_E;
        #pragma unroll
        for (int l = 0; l < 2; l++) {
            int q = tid + l * 256;
            int row = q >> 2, c8 = (q & 3) * 8;
            cp16(&sA[row * SSTR + c8], Ah + (size_t)(m0 + row) * GCN + kc + c8);
            cp16(&sB[row * SSTR + c8], Bh + (size_t)(n0 + row) * GCN + kc + c8);
        }
    };

    load_stage(0, 0); CP_COMMIT();
    load_stage(1, 1); CP_COMMIT();

    for (int kt = 0; kt < NBASE; kt++) {
        CP_WAIT1();
        __syncthreads();
        if (kt + 2 < NBASE) load_stage(kt + 2, (kt + 2) % NSTAGE);
        CP_COMMIT();

        const int s = kt % NSTAGE;
        const __half* sA = dynsmem + s * STAGE_ELEMS;
        const __half* sB = sA + TILE_E;

        #pragma unroll
        for (int kk = 0; kk < BK; kk += 16) {
            unsigned a[4][4], b[2][4];
            #pragma unroll
            for (int mt = 0; mt < 4; mt++)
                ldsm4(a[mt][0], a[mt][1], a[mt][2], a[mt][3],
                      &sA[(wmBase + mt * 16 + aRow) * SSTR + kk + aK]);
            #pragma unroll
            for (int ntp = 0; ntp < 2; ntp++)
                ldsm4(b[ntp][0], b[ntp][1], b[ntp][2], b[ntp][3],
                      &sB[(wnBase + ntp * 16 + bRow) * SSTR + kk + bK]);
            #pragma unroll
            for (int mt = 0; mt < 4; mt++)
                #pragma unroll
                for (int nt = 0; nt < 4; nt++) {
                    unsigned b0 = b[nt >> 1][(nt & 1) * 2];
                    unsigned b1 = b[nt >> 1][(nt & 1) * 2 + 1];
                    asm volatile(
                        "mma.sync.aligned.m16n8k16.row.col.f32.f16.f16.f32 "
                        "{%0,%1,%2,%3}, {%4,%5,%6,%7}, {%8,%9}, {%0,%1,%2,%3};\n"
                        : "+f"(acc[mt][nt][0]), "+f"(acc[mt][nt][1]),
                          "+f"(acc[mt][nt][2]), "+f"(acc[mt][nt][3])
                        : "r"(a[mt][0]), "r"(a[mt][1]), "r"(a[mt][2]), "r"(a[mt][3]),
                          "r"(b0), "r"(b1));
                }
        }
    }

    #pragma unroll
    for (int mt = 0; mt < 4; mt++) {
        int row = m0 + wmBase + mt * 16 + (lane >> 2);
        #pragma unroll
        for (int nt = 0; nt < 4; nt++) {
            int col = n0 + wnBase + nt * 8 + (lane & 3) * 2;
            if (col < PF) {
                *(float2*)&C[(size_t)row * PF + col] =
                    make_float2(acc[mt][nt][0], acc[mt][nt][1]);
                *(float2*)&C[(size_t)(row + 8) * PF + col] =
                    make_float2(acc[mt][nt][2], acc[mt][nt][3]);
            }
        }
    }
}

// ---------------- packed f32x2 helpers ---------------------------------------
__device__ __forceinline__ unsigned long long f2add(unsigned long long a,
                                                    unsigned long long b) {
    unsigned long long r;
    asm("add.rn.f32x2 %0, %1, %2;" : "=l"(r) : "l"(a), "l"(b));
    return r;
}
__device__ __forceinline__ unsigned long long f2fma(unsigned long long a,
                                                    unsigned long long b,
                                                    unsigned long long c) {
    unsigned long long r;
    asm("fma.rn.f32x2 %0, %1, %2, %3;" : "=l"(r) : "l"(a), "l"(b), "l"(c));
    return r;
}
__device__ __forceinline__ unsigned long long f2relu(unsigned long long v) {
    float lo, hi;
    asm("mov.b64 {%0,%1}, %2;" : "=f"(lo), "=f"(hi) : "l"(v));
    lo = fmaxf(lo, 0.f);
    hi = fmaxf(hi, 0.f);
    unsigned long long r;
    asm("mov.b64 %0, {%1,%2};" : "=l"(r) : "f"(lo), "f"(hi));
    return r;
}
__device__ __forceinline__ float f2sum(unsigned long long v) {
    float lo, hi;
    asm("mov.b64 {%0,%1}, %2;" : "=f"(lo), "=f"(hi) : "l"(v));
    return lo + hi;
}

// ---------------- epilogue: warp/(b,i,4j), packed f32x2, W2 in smem ----------
#define WPI 5
#define TOTW (B_ * L_ * WPI)

__global__ void __launch_bounds__(256)
epilogue_kernel(const float* __restrict__ W2, const float* __restrict__ b2,
                float* __restrict__ out) {
    __shared__ __align__(16) float sW[PF];

    const int tid  = threadIdx.x;
    const int lane = tid & 31;
    const int wid  = tid >> 5;

    {
        const float4* src = (const float4*)W2;
        float4* dst = (float4*)sW;
        for (int q = tid; q < PF / 4; q += 256) dst[q] = src[q];
    }
    __syncthreads();

    int gw = blockIdx.x * 8 + wid;
    if (gw >= TOTW) return;
    int b   = gw / (L_ * WPI);
    int rem = gw - b * (L_ * WPI);
    int i   = rem / WPI;
    int k   = rem - i * WPI;

    int lo = i - KW; if (lo < 0) lo = 0;
    int hi = i + KW; if (hi > L_ - 1) hi = L_ - 1;
    int jstart = lo + 4 * k;
    if (jstart > hi) return;
    int cnt = hi - jstart + 1; if (cnt > 4) cnt = 4;

    int js0 = jstart;
    int js1 = jstart + 1 > hi ? hi : jstart + 1;
    int js2 = jstart + 2 > hi ? hi : jstart + 2;
    int js3 = jstart + 3 > hi ? hi : jstart + 3;

    const ulonglong2* __restrict__ ac0 =
        (const ulonglong2*)(g_Acau + (size_t)(b * L_ + js0) * PF);
    const ulonglong2* __restrict__ ac1 =
        (const ulonglong2*)(g_Acau + (size_t)(b * L_ + js1) * PF);
    const ulonglong2* __restrict__ ac2 =
        (const ulonglong2*)(g_Acau + (size_t)(b * L_ + js2) * PF);
    const ulonglong2* __restrict__ ac3 =
        (const ulonglong2*)(g_Acau + (size_t)(b * L_ + js3) * PF);
    const ulonglong2* __restrict__ ap0 =
        (const ulonglong2*)(g_Apos + (size_t)(js0 - i + KW) * PF);
    const ulonglong2* __restrict__ ap1 =
        (const ulonglong2*)(g_Apos + (size_t)(js1 - i + KW) * PF);
    const ulonglong2* __restrict__ ap2 =
        (const ulonglong2*)(g_Apos + (size_t)(js2 - i + KW) * PF);
    const ulonglong2* __restrict__ ap3 =
        (const ulonglong2*)(g_Apos + (size_t)(js3 - i + KW) * PF);
    const ulonglong2* __restrict__ sw2 = (const ulonglong2*)sW;

    // emo row into registers (packed)
    ulonglong2 er[9];
    {
        const ulonglong2* ae =
            (const ulonglong2*)(g_Aemo + (size_t)(b * L_ + i) * PF);
        #pragma unroll
        for (int t = 0; t < 9; t++) {
            int c4 = t * 32 + lane;
            if (c4 < PF / 4) er[t] = ae[c4];
            else { er[t].x = 0ull; er[t].y = 0ull; }
        }
    }
    const float bias = __ldg(b2);

    unsigned long long s0a = 0, s0b = 0, s1a = 0, s1b = 0;
    unsigned long long s2a = 0, s2b = 0, s3a = 0, s3b = 0;
    #pragma unroll
    for (int t = 0; t < 9; t++) {
        int c4 = t * 32 + lane;
        if (c4 < PF / 4) {
            ulonglong2 e = er[t];
            ulonglong2 w = sw2[c4];
            {
                ulonglong2 c = ac0[c4]; ulonglong2 q = ap0[c4];
                s0a = f2fma(f2relu(f2add(f2add(e.x, c.x), q.x)), w.x, s0a);
                s0b = f2fma(f2relu(f2add(f2add(e.y, c.y), q.y)), w.y, s0b);
            }
            {
                ulonglong2 c = ac1[c4]; ulonglong2 q = ap1[c4];
                s1a = f2fma(f2relu(f2add(f2add(e.x, c.x), q.x)), w.x, s1a);
                s1b = f2fma(f2relu(f2add(f2add(e.y, c.y), q.y)), w.y, s1b);
            }
            {
                ulonglong2 c = ac2[c4]; ulonglong2 q = ap2[c4];
                s2a = f2fma(f2relu(f2add(f2add(e.x, c.x), q.x)), w.x, s2a);
                s2b = f2fma(f2relu(f2add(f2add(e.y, c.y), q.y)), w.y, s2b);
            }
            {
                ulonglong2 c = ac3[c4]; ulonglong2 q = ap3[c4];
                s3a = f2fma(f2relu(f2add(f2add(e.x, c.x), q.x)), w.x, s3a);
                s3b = f2fma(f2relu(f2add(f2add(e.y, c.y), q.y)), w.y, s3b);
            }
        }
    }
    float s0 = f2sum(s0a) + f2sum(s0b);
    float s1 = f2sum(s1a) + f2sum(s1b);
    float s2 = f2sum(s2a) + f2sum(s2b);
    float s3 = f2sum(s3a) + f2sum(s3b);

    #pragma unroll
    for (int o = 16; o > 0; o >>= 1) {
        s0 += __shfl_xor_sync(0xFFFFFFFF, s0, o);
        s1 += __shfl_xor_sync(0xFFFFFFFF, s1, o);
        s2 += __shfl_xor_sync(0xFFFFFFFF, s2, o);
        s3 += __shfl_xor_sync(0xFFFFFFFF, s3, o);
    }
    if (lane == 0) {
        int pb = b * NPAIR + g_poff[i] + (jstart - lo);
        out[pb] = s0 + bias;
        if (cnt > 1) out[pb + 1] = s1 + bias;
        if (cnt > 2) out[pb + 2] = s2 + bias;
        if (cnt > 3) out[pb + 3] = s3 + bias;
    }
}

// ---------------- launch ------------------------------------------------------
extern "C" void kernel_launch(void* const* d_in, const int* in_sizes, int n_in,
                              void* d_out, int out_size) {
    const float* h_emo  = (const float*)d_in[0];
    const float* h_cau  = (const float*)d_in[1];
    const float* pos    = (const float*)d_in[2];
    const float* W1     = (const float*)d_in[3];
    const float* b1     = (const float*)d_in[4];
    const float* W2     = (const float*)d_in[5];
    const float* b2     = (const float*)d_in[6];
    float* out = (float*)d_out;

    const int gemm_smem = NSTAGE * STAGE_ELEMS * (int)sizeof(__half);
    static bool configured = false;
    if (!configured) {
        cudaFuncSetAttribute(mma_gemm_kernel,
                             cudaFuncAttributeMaxDynamicSharedMemorySize, gemm_smem);
        configured = true;
    }

    init_pairs_kernel<<<1, 128>>>(out, out_size);
    init_f_kernel<<<(NREL * PE + 255) / 256, 256>>>(pos);
    init_apos_kernel<<<(NREL * PF + 255) / 256, 256>>>(W1, b1);
    conv_all_kernel<<<XBLK + WBLK, 256>>>(h_emo, h_cau, W1);

    dim3 ggrid(PFP / BN, M_ / BM, 2);   // (9, 16, 2)
    mma_gemm_kernel<<<ggrid, 256, gemm_smem>>>();

    int blocks = (TOTW * 32 + 255) / 256;   // 1280 blocks
    epilogue_kernel<<<blocks, 256>>>(W2, b2, out);
}